// round 1
// baseline (speedup 1.0000x reference)
#include <cuda_runtime.h>
#include <math.h>

#define BB 2
#define SS 2048
#define HID 1024
#define NH 16
#define DD 64
#define MM (BB*SS)          // 4096

// ---------------- scratch (no allocation allowed) ----------------
__device__ float g_q[BB*SS*HID];
__device__ float g_k[BB*SS*HID];
__device__ float g_v[BB*SS*HID];
__device__ float g_ctx[BB*SS*HID];

// ---------------- GEMM: C[M][N] = A[M][K] @ W[N][K]^T ----------------
// 128x128x16 tile, 256 threads, 8x8 micro-tile.
__global__ __launch_bounds__(256) void gemm_nt_kernel(
    const float* __restrict__ A, const float* __restrict__ W,
    float* __restrict__ C, int M, int N, int K)
{
    __shared__ float As[16][128];
    __shared__ float Bs[16][128];

    const int tx = threadIdx.x;       // 0..15
    const int ty = threadIdx.y;       // 0..15
    const int tid = ty * 16 + tx;
    const int m0 = blockIdx.y * 128;
    const int n0 = blockIdx.x * 128;

    float acc[8][8];
#pragma unroll
    for (int i = 0; i < 8; i++)
#pragma unroll
        for (int j = 0; j < 8; j++) acc[i][j] = 0.0f;

    for (int k0 = 0; k0 < K; k0 += 16) {
        // load A tile (128 rows x 16 cols), store transposed As[k][m]
#pragma unroll
        for (int it = 0; it < 2; it++) {
            int e = tid + it * 256;          // 0..511 float4 units
            int row = e >> 2;                // 0..127
            int cb = e & 3;                  // 0..3
            float4 v4 = *(const float4*)&A[(size_t)(m0 + row) * K + k0 + cb * 4];
            As[cb * 4 + 0][row] = v4.x;
            As[cb * 4 + 1][row] = v4.y;
            As[cb * 4 + 2][row] = v4.z;
            As[cb * 4 + 3][row] = v4.w;
        }
        // load W tile (128 rows x 16 cols), store transposed Bs[k][n]
#pragma unroll
        for (int it = 0; it < 2; it++) {
            int e = tid + it * 256;
            int row = e >> 2;
            int cb = e & 3;
            float4 v4 = *(const float4*)&W[(size_t)(n0 + row) * K + k0 + cb * 4];
            Bs[cb * 4 + 0][row] = v4.x;
            Bs[cb * 4 + 1][row] = v4.y;
            Bs[cb * 4 + 2][row] = v4.z;
            Bs[cb * 4 + 3][row] = v4.w;
        }
        __syncthreads();

#pragma unroll
        for (int kk = 0; kk < 16; kk++) {
            float a[8], b[8];
            *(float4*)&a[0] = *(const float4*)&As[kk][ty * 8];
            *(float4*)&a[4] = *(const float4*)&As[kk][ty * 8 + 4];
            *(float4*)&b[0] = *(const float4*)&Bs[kk][tx * 8];
            *(float4*)&b[4] = *(const float4*)&Bs[kk][tx * 8 + 4];
#pragma unroll
            for (int i = 0; i < 8; i++)
#pragma unroll
                for (int j = 0; j < 8; j++)
                    acc[i][j] += a[i] * b[j];
        }
        __syncthreads();
    }

#pragma unroll
    for (int i = 0; i < 8; i++) {
        int row = m0 + ty * 8 + i;
#pragma unroll
        for (int j4 = 0; j4 < 2; j4++) {
            float4 v4;
            v4.x = acc[i][j4 * 4 + 0];
            v4.y = acc[i][j4 * 4 + 1];
            v4.z = acc[i][j4 * 4 + 2];
            v4.w = acc[i][j4 * 4 + 3];
            *(float4*)&C[(size_t)row * N + n0 + tx * 8 + j4 * 4] = v4;
        }
    }
}

// ---------------- RoPE on q and k in place ----------------
__global__ void rope_kernel(float* __restrict__ q, float* __restrict__ k,
                            const float* __restrict__ cosT,
                            const float* __restrict__ sinT)
{
    int idx = blockIdx.x * blockDim.x + threadIdx.x;   // over B*S*H*32
    if (idx >= BB * SS * NH * (DD / 2)) return;
    int p = idx & 31;
    int s = (idx >> 9) & (SS - 1);
    float c  = cosT[s * 32 + p];
    float sn = sinT[s * 32 + p];
    int base = idx * 2;
    float a = q[base], b = q[base + 1];
    q[base]     = a * c - b * sn;
    q[base + 1] = a * sn + b * c;
    a = k[base]; b = k[base + 1];
    k[base]     = a * c - b * sn;
    k[base + 1] = a * sn + b * c;
}

// ---------------- Flash attention (causal) ----------------
// grid: (S/64, H, B); block 16x16. Q/K/V layout [b][s][h][d].
#define SMS 68   // smem row stride (floats)

__global__ __launch_bounds__(256) void attn_kernel(
    const float* __restrict__ q, const float* __restrict__ k,
    const float* __restrict__ v, float* __restrict__ ctx)
{
    extern __shared__ float sm[];
    float* Qt = sm;                  // [d][r] 64x68
    float* Kt = sm + 64 * SMS;       // [d][c] 64x68, reused as Pt[c][r]
    float* Vs = sm + 2 * 64 * SMS;   // [c][d] 64x68

    const int qi = blockIdx.x;
    const int h  = blockIdx.y;
    const int b  = blockIdx.z;
    const int tx = threadIdx.x, ty = threadIdx.y;
    const int tid = ty * 16 + tx;
    const float scaling = 0.125f;    // D^-0.5

    // load Q tile transposed: Qt[d][r]
#pragma unroll
    for (int it = 0; it < 4; it++) {
        int e = tid + it * 256;                 // 0..1023 float4 units
        int r = e >> 4;                         // 0..63
        int d4 = (e & 15) * 4;                  // 0..60
        float4 v4 = *(const float4*)&q[(((size_t)b * SS + qi * 64 + r) * NH + h) * DD + d4];
        Qt[(d4 + 0) * SMS + r] = v4.x;
        Qt[(d4 + 1) * SMS + r] = v4.y;
        Qt[(d4 + 2) * SMS + r] = v4.z;
        Qt[(d4 + 3) * SMS + r] = v4.w;
    }

    float m[4], l[4], o[4][4];
#pragma unroll
    for (int i = 0; i < 4; i++) {
        m[i] = -1e30f; l[i] = 0.0f;
#pragma unroll
        for (int j = 0; j < 4; j++) o[i][j] = 0.0f;
    }

    for (int jt = 0; jt <= qi; jt++) {
        __syncthreads();   // previous iter's Pt/Vs reads done (also covers Qt writes on iter 0)
        // load K (transposed) and V tiles
#pragma unroll
        for (int it = 0; it < 4; it++) {
            int e = tid + it * 256;
            int r = e >> 4;
            int d4 = (e & 15) * 4;
            size_t gbase = (((size_t)b * SS + jt * 64 + r) * NH + h) * DD + d4;
            float4 kv = *(const float4*)&k[gbase];
            Kt[(d4 + 0) * SMS + r] = kv.x;
            Kt[(d4 + 1) * SMS + r] = kv.y;
            Kt[(d4 + 2) * SMS + r] = kv.z;
            Kt[(d4 + 3) * SMS + r] = kv.w;
            float4 vv = *(const float4*)&v[gbase];
            *(float4*)&Vs[r * SMS + d4] = vv;
        }
        __syncthreads();

        // scores: s4[i][j] = sum_d Qt[d][ty*4+i] * Kt[d][tx*4+j]
        float s4[4][4];
#pragma unroll
        for (int i = 0; i < 4; i++)
#pragma unroll
            for (int j = 0; j < 4; j++) s4[i][j] = 0.0f;

#pragma unroll 4
        for (int d = 0; d < 64; d++) {
            float a[4], bb[4];
            *(float4*)a  = *(const float4*)&Qt[d * SMS + ty * 4];
            *(float4*)bb = *(const float4*)&Kt[d * SMS + tx * 4];
#pragma unroll
            for (int i = 0; i < 4; i++)
#pragma unroll
                for (int j = 0; j < 4; j++)
                    s4[i][j] += a[i] * bb[j];
        }

        // scale + causal mask
        const int qg0 = qi * 64 + ty * 4;
        const int kg0 = jt * 64 + tx * 4;
#pragma unroll
        for (int i = 0; i < 4; i++)
#pragma unroll
            for (int j = 0; j < 4; j++) {
                float sv = s4[i][j] * scaling;
                if (kg0 + j > qg0 + i) sv = -1e9f;
                s4[i][j] = sv;
            }

        // online softmax: row max / sum via shfl over the 16 tx lanes
        float rsum[4];
#pragma unroll
        for (int i = 0; i < 4; i++) {
            float tmax = fmaxf(fmaxf(s4[i][0], s4[i][1]), fmaxf(s4[i][2], s4[i][3]));
#pragma unroll
            for (int msk = 1; msk < 16; msk <<= 1)
                tmax = fmaxf(tmax, __shfl_xor_sync(0xffffffffu, tmax, msk));
            float mn = fmaxf(m[i], tmax);
            float alpha = __expf(m[i] - mn);
            m[i] = mn;
            float rs = 0.0f;
#pragma unroll
            for (int j = 0; j < 4; j++) {
                float p = __expf(s4[i][j] - mn);
                s4[i][j] = p;
                rs += p;
            }
#pragma unroll
            for (int msk = 1; msk < 16; msk <<= 1)
                rs += __shfl_xor_sync(0xffffffffu, rs, msk);
            rsum[i] = rs;
            l[i] = l[i] * alpha + rs;
#pragma unroll
            for (int j = 0; j < 4; j++) o[i][j] *= alpha;
        }
        (void)rsum;

        __syncthreads();   // everyone done reading Kt
        // write P transposed into Kt buffer: Pt[c][r]
        float* Pt = Kt;
#pragma unroll
        for (int j = 0; j < 4; j++) {
            float4 pv;
            pv.x = s4[0][j]; pv.y = s4[1][j]; pv.z = s4[2][j]; pv.w = s4[3][j];
            *(float4*)&Pt[(tx * 4 + j) * SMS + ty * 4] = pv;
        }
        __syncthreads();

        // O += P @ V : o[i][j] += sum_c Pt[c][ty*4+i] * Vs[c][tx*4+j]
#pragma unroll 4
        for (int c = 0; c < 64; c++) {
            float a[4], bb[4];
            *(float4*)a  = *(const float4*)&Pt[c * SMS + ty * 4];
            *(float4*)bb = *(const float4*)&Vs[c * SMS + tx * 4];
#pragma unroll
            for (int i = 0; i < 4; i++)
#pragma unroll
                for (int j = 0; j < 4; j++)
                    o[i][j] += a[i] * bb[j];
        }
    }

    // epilogue: normalize and write ctx[b][s][h][d]
#pragma unroll
    for (int i = 0; i < 4; i++) {
        float inv = 1.0f / l[i];
        float4 v4;
        v4.x = o[i][0] * inv;
        v4.y = o[i][1] * inv;
        v4.z = o[i][2] * inv;
        v4.w = o[i][3] * inv;
        size_t row = ((size_t)b * SS + qi * 64 + ty * 4 + i) * NH + h;
        *(float4*)&ctx[row * DD + tx * 4] = v4;
    }
}

// ---------------- host ----------------
extern "C" void kernel_launch(void* const* d_in, const int* in_sizes, int n_in,
                              void* d_out, int out_size)
{
    const float* hidden = (const float*)d_in[0];
    const float* cosT   = (const float*)d_in[1];
    const float* sinT   = (const float*)d_in[2];
    // d_in[3] = attn_mask (causal -1e9), implemented analytically
    const float* Wq = (const float*)d_in[4];
    const float* Wk = (const float*)d_in[5];
    const float* Wv = (const float*)d_in[6];
    const float* Wo = (const float*)d_in[7];
    float* out = (float*)d_out;

    float *q, *k, *v, *ctx;
    cudaGetSymbolAddress((void**)&q,   g_q);
    cudaGetSymbolAddress((void**)&k,   g_k);
    cudaGetSymbolAddress((void**)&v,   g_v);
    cudaGetSymbolAddress((void**)&ctx, g_ctx);

    dim3 gThreads(16, 16);
    dim3 gGrid(HID / 128, MM / 128);   // (8, 32)

    gemm_nt_kernel<<<gGrid, gThreads>>>(hidden, Wq, q, MM, HID, HID);
    gemm_nt_kernel<<<gGrid, gThreads>>>(hidden, Wk, k, MM, HID, HID);
    gemm_nt_kernel<<<gGrid, gThreads>>>(hidden, Wv, v, MM, HID, HID);

    int nrope = BB * SS * NH * (DD / 2);
    rope_kernel<<<(nrope + 255) / 256, 256>>>(q, k, cosT, sinT);

    int smem = 3 * 64 * SMS * sizeof(float);   // 52224 B
    cudaFuncSetAttribute(attn_kernel, cudaFuncAttributeMaxDynamicSharedMemorySize, smem);
    dim3 aGrid(SS / 64, NH, BB);               // (32, 16, 2)
    attn_kernel<<<aGrid, gThreads, smem>>>(q, k, v, ctx);

    gemm_nt_kernel<<<gGrid, gThreads>>>(ctx, Wo, out, MM, HID, HID);
}

// round 3
// speedup vs baseline: 1.4516x; 1.4516x over previous
#include <cuda_runtime.h>
#include <cuda_bf16.h>
#include <cstdint>
#include <math.h>

#define BB 2
#define SS 2048
#define HID 1024
#define NH 16
#define DD 64
#define MM (BB*SS)          // 4096

// ---------------- scratch (no allocation allowed) ----------------
__device__ float g_q[BB*SS*HID];
__device__ float g_k[BB*SS*HID];
__device__ float g_v[BB*SS*HID];
__device__ float g_ctx[BB*SS*HID];

__device__ __nv_bfloat16 g_hid_h[MM*HID];
__device__ __nv_bfloat16 g_hid_l[MM*HID];
__device__ __nv_bfloat16 g_w_h[4][HID*HID];
__device__ __nv_bfloat16 g_w_l[4][HID*HID];
__device__ __nv_bfloat16 g_ctx_h[MM*HID];
__device__ __nv_bfloat16 g_ctx_l[MM*HID];

// ================= helpers =================
__device__ __forceinline__ uint32_t smem_to_u32(const void* smem_ptr) {
    uint32_t addr;
    asm("{ .reg .u64 tmp; cvta.to.shared.u64 tmp, %1; cvt.u32.u64 %0, tmp; }"
        : "=r"(addr) : "l"(smem_ptr));
    return addr;
}
__device__ __forceinline__ void ldm_x4(uint32_t* r, uint32_t addr) {
    asm volatile("ldmatrix.sync.aligned.m8n8.x4.shared.b16 {%0,%1,%2,%3}, [%4];"
        : "=r"(r[0]), "=r"(r[1]), "=r"(r[2]), "=r"(r[3]) : "r"(addr));
}
__device__ __forceinline__ void mma16816(float* c, const uint32_t* a, const uint32_t* b) {
    asm volatile("mma.sync.aligned.m16n8k16.row.col.f32.bf16.bf16.f32 "
        "{%0,%1,%2,%3}, {%4,%5,%6,%7}, {%8,%9}, {%0,%1,%2,%3};"
        : "+f"(c[0]), "+f"(c[1]), "+f"(c[2]), "+f"(c[3])
        : "r"(a[0]), "r"(a[1]), "r"(a[2]), "r"(a[3]), "r"(b[0]), "r"(b[1]));
}

// ================= fp32 -> bf16 hi/lo split =================
__global__ void split_kernel(const float* __restrict__ x,
                             __nv_bfloat16* __restrict__ hi,
                             __nv_bfloat16* __restrict__ lo, int n4)
{
    int i = blockIdx.x * blockDim.x + threadIdx.x;
    if (i >= n4) return;
    float4 v = ((const float4*)x)[i];
    float vv[4] = {v.x, v.y, v.z, v.w};
    __nv_bfloat16 h[4], l[4];
#pragma unroll
    for (int j = 0; j < 4; j++) {
        h[j] = __float2bfloat16(vv[j]);
        l[j] = __float2bfloat16(vv[j] - __bfloat162float(h[j]));
    }
    __nv_bfloat162* hp = (__nv_bfloat162*)hi;
    __nv_bfloat162* lp = (__nv_bfloat162*)lo;
    hp[i * 2 + 0] = __nv_bfloat162(h[0], h[1]);
    hp[i * 2 + 1] = __nv_bfloat162(h[2], h[3]);
    lp[i * 2 + 0] = __nv_bfloat162(l[0], l[1]);
    lp[i * 2 + 1] = __nv_bfloat162(l[2], l[3]);
}

// ================= HMMA GEMM =================
// C[4096][1024] = A[4096][1024] @ W[1024][1024]^T, split bf16 3-term.
// CTA 128x128, 8 warps (2m x 4n), warp tile 64x32, K-chunk 32.
// smem row stride = 40 bf16 (80 B) -> conflict-free ldmatrix.
#define KC 32
#define NITER (HID / KC)           // 32
#define SROW 80                    // bytes per smem row
#define SBUF (128 * SROW)          // 10240 B per logical buffer

__global__ __launch_bounds__(256, 1) void gemm_bf16_kernel(
    const __nv_bfloat16* __restrict__ Ah, const __nv_bfloat16* __restrict__ Al,
    const __nv_bfloat16* __restrict__ Bh, const __nv_bfloat16* __restrict__ Bl,
    float* __restrict__ C)
{
    __shared__ __align__(16) unsigned char smem[4 * SBUF];   // Ah | Al | Bh | Bl

    const int tid  = threadIdx.x;
    const int wid  = tid >> 5;
    const int lane = tid & 31;
    const int wm   = wid >> 2;     // 0..1
    const int wn   = wid & 3;      // 0..3
    const int m0   = blockIdx.y * 128;
    const int n0   = blockIdx.x * 128;

    const uint32_t sb = smem_to_u32(smem);
    const uint32_t sA  = sb;
    const uint32_t sAl = sb + SBUF;
    const uint32_t sB  = sb + 2 * SBUF;
    const uint32_t sBl = sb + 3 * SBUF;

    // ldmatrix per-thread address components
    const int rowA  = lane & 15;               // A: lanes 0-15 rows, 16-31 k+8
    const int kofsA = (lane >> 4) * 16;        // byte offset (8 bf16)
    const int rowB  = (lane & 7) + ((lane >> 4) & 1) * 8;
    const int kofsB = ((lane >> 3) & 1) * 16;

    float acc[4][4][4];
#pragma unroll
    for (int i = 0; i < 4; i++)
#pragma unroll
        for (int j = 0; j < 4; j++)
#pragma unroll
            for (int r = 0; r < 4; r++) acc[i][j][r] = 0.0f;

    // staging registers (prefetch)
    uint4 stA[2], stAl[2], stB[2], stBl[2];

    const int row_s = tid >> 2;         // 0..63  (tid) / 64..127 (tid+256)
    const int kc_s  = tid & 3;

#pragma unroll
    for (int i = 0; i < 2; i++) {
        int row = row_s + i * 64;
        size_t ga = (size_t)(m0 + row) * HID + kc_s * 8;
        size_t gb = (size_t)(n0 + row) * HID + kc_s * 8;
        stA[i]  = *(const uint4*)(Ah + ga);
        stAl[i] = *(const uint4*)(Al + ga);
        stB[i]  = *(const uint4*)(Bh + gb);
        stBl[i] = *(const uint4*)(Bl + gb);
    }

    for (int it = 0; it < NITER; it++) {
        __syncthreads();
#pragma unroll
        for (int i = 0; i < 2; i++) {
            int row = row_s + i * 64;
            int off = row * SROW + kc_s * 16;
            *(uint4*)(smem + off)            = stA[i];
            *(uint4*)(smem + SBUF + off)     = stAl[i];
            *(uint4*)(smem + 2 * SBUF + off) = stB[i];
            *(uint4*)(smem + 3 * SBUF + off) = stBl[i];
        }
        __syncthreads();

        if (it + 1 < NITER) {
            int k0 = (it + 1) * KC;
#pragma unroll
            for (int i = 0; i < 2; i++) {
                int row = row_s + i * 64;
                size_t ga = (size_t)(m0 + row) * HID + k0 + kc_s * 8;
                size_t gb = (size_t)(n0 + row) * HID + k0 + kc_s * 8;
                stA[i]  = *(const uint4*)(Ah + ga);
                stAl[i] = *(const uint4*)(Al + ga);
                stB[i]  = *(const uint4*)(Bh + gb);
                stBl[i] = *(const uint4*)(Bl + gb);
            }
        }

#pragma unroll
        for (int kk = 0; kk < 2; kk++) {
            const int kb = kk * 32;   // byte offset of this k16 within the row

            uint32_t ah[4][4], bh[4][2];
            // A hi fragments: 4 m-tiles
#pragma unroll
            for (int mt = 0; mt < 4; mt++) {
                uint32_t addr = sA + (wm * 64 + mt * 16 + rowA) * SROW + kb + kofsA;
                ldm_x4(ah[mt], addr);
            }
            // B hi fragments: 2 x4 loads cover 4 n-tiles
#pragma unroll
            for (int nt2 = 0; nt2 < 2; nt2++) {
                uint32_t t[4];
                uint32_t addr = sB + (wn * 32 + nt2 * 16 + rowB) * SROW + kb + kofsB;
                ldm_x4(t, addr);
                bh[nt2 * 2 + 0][0] = t[0]; bh[nt2 * 2 + 0][1] = t[1];
                bh[nt2 * 2 + 1][0] = t[2]; bh[nt2 * 2 + 1][1] = t[3];
            }
#pragma unroll
            for (int mt = 0; mt < 4; mt++)
#pragma unroll
                for (int nt = 0; nt < 4; nt++)
                    mma16816(acc[mt][nt], ah[mt], bh[nt]);

            // B lo term (Ah * Bl)
            {
                uint32_t bl[4][2];
#pragma unroll
                for (int nt2 = 0; nt2 < 2; nt2++) {
                    uint32_t t[4];
                    uint32_t addr = sBl + (wn * 32 + nt2 * 16 + rowB) * SROW + kb + kofsB;
                    ldm_x4(t, addr);
                    bl[nt2 * 2 + 0][0] = t[0]; bl[nt2 * 2 + 0][1] = t[1];
                    bl[nt2 * 2 + 1][0] = t[2]; bl[nt2 * 2 + 1][1] = t[3];
                }
#pragma unroll
                for (int mt = 0; mt < 4; mt++)
#pragma unroll
                    for (int nt = 0; nt < 4; nt++)
                        mma16816(acc[mt][nt], ah[mt], bl[nt]);
            }

            // A lo term (Al * Bh)
            {
                uint32_t al[4][4];
#pragma unroll
                for (int mt = 0; mt < 4; mt++) {
                    uint32_t addr = sAl + (wm * 64 + mt * 16 + rowA) * SROW + kb + kofsA;
                    ldm_x4(al[mt], addr);
                }
#pragma unroll
                for (int mt = 0; mt < 4; mt++)
#pragma unroll
                    for (int nt = 0; nt < 4; nt++)
                        mma16816(acc[mt][nt], al[mt], bh[nt]);
            }
        }
    }

    // epilogue: acc frag (m16n8): c0,c1 at (lane/4, lane%4*2), c2,c3 at (+8 rows)
    const int rr = lane >> 2;
    const int cc = (lane & 3) * 2;
#pragma unroll
    for (int mt = 0; mt < 4; mt++) {
#pragma unroll
        for (int nt = 0; nt < 4; nt++) {
            int r = m0 + wm * 64 + mt * 16 + rr;
            int c = n0 + wn * 32 + nt * 8 + cc;
            float2 v0 = make_float2(acc[mt][nt][0], acc[mt][nt][1]);
            float2 v1 = make_float2(acc[mt][nt][2], acc[mt][nt][3]);
            *(float2*)&C[(size_t)r * HID + c]       = v0;
            *(float2*)&C[(size_t)(r + 8) * HID + c] = v1;
        }
    }
}

// ---------------- RoPE on q and k in place ----------------
__global__ void rope_kernel(float* __restrict__ q, float* __restrict__ k,
                            const float* __restrict__ cosT,
                            const float* __restrict__ sinT)
{
    int idx = blockIdx.x * blockDim.x + threadIdx.x;
    if (idx >= BB * SS * NH * (DD / 2)) return;
    int p = idx & 31;
    int s = (idx >> 9) & (SS - 1);
    float c  = cosT[s * 32 + p];
    float sn = sinT[s * 32 + p];
    int base = idx * 2;
    float a = q[base], b = q[base + 1];
    q[base]     = a * c - b * sn;
    q[base + 1] = a * sn + b * c;
    a = k[base]; b = k[base + 1];
    k[base]     = a * c - b * sn;
    k[base + 1] = a * sn + b * c;
}

// ---------------- Flash attention (causal, fp32) ----------------
#define SMS 68

__global__ __launch_bounds__(256) void attn_kernel(
    const float* __restrict__ q, const float* __restrict__ k,
    const float* __restrict__ v, float* __restrict__ ctx)
{
    extern __shared__ float sm[];
    float* Qt = sm;
    float* Kt = sm + 64 * SMS;
    float* Vs = sm + 2 * 64 * SMS;

    const int qi = blockIdx.x;
    const int h  = blockIdx.y;
    const int b  = blockIdx.z;
    const int tx = threadIdx.x, ty = threadIdx.y;
    const int tid = ty * 16 + tx;
    const float scaling = 0.125f;

#pragma unroll
    for (int it = 0; it < 4; it++) {
        int e = tid + it * 256;
        int r = e >> 4;
        int d4 = (e & 15) * 4;
        float4 v4 = *(const float4*)&q[(((size_t)b * SS + qi * 64 + r) * NH + h) * DD + d4];
        Qt[(d4 + 0) * SMS + r] = v4.x;
        Qt[(d4 + 1) * SMS + r] = v4.y;
        Qt[(d4 + 2) * SMS + r] = v4.z;
        Qt[(d4 + 3) * SMS + r] = v4.w;
    }

    float m[4], l[4], o[4][4];
#pragma unroll
    for (int i = 0; i < 4; i++) {
        m[i] = -1e30f; l[i] = 0.0f;
#pragma unroll
        for (int j = 0; j < 4; j++) o[i][j] = 0.0f;
    }

    for (int jt = 0; jt <= qi; jt++) {
        __syncthreads();
#pragma unroll
        for (int it = 0; it < 4; it++) {
            int e = tid + it * 256;
            int r = e >> 4;
            int d4 = (e & 15) * 4;
            size_t gbase = (((size_t)b * SS + jt * 64 + r) * NH + h) * DD + d4;
            float4 kv = *(const float4*)&k[gbase];
            Kt[(d4 + 0) * SMS + r] = kv.x;
            Kt[(d4 + 1) * SMS + r] = kv.y;
            Kt[(d4 + 2) * SMS + r] = kv.z;
            Kt[(d4 + 3) * SMS + r] = kv.w;
            float4 vv = *(const float4*)&v[gbase];
            *(float4*)&Vs[r * SMS + d4] = vv;
        }
        __syncthreads();

        float s4[4][4];
#pragma unroll
        for (int i = 0; i < 4; i++)
#pragma unroll
            for (int j = 0; j < 4; j++) s4[i][j] = 0.0f;

#pragma unroll 4
        for (int d = 0; d < 64; d++) {
            float a[4], bb[4];
            *(float4*)a  = *(const float4*)&Qt[d * SMS + ty * 4];
            *(float4*)bb = *(const float4*)&Kt[d * SMS + tx * 4];
#pragma unroll
            for (int i = 0; i < 4; i++)
#pragma unroll
                for (int j = 0; j < 4; j++)
                    s4[i][j] += a[i] * bb[j];
        }

        const int qg0 = qi * 64 + ty * 4;
        const int kg0 = jt * 64 + tx * 4;
#pragma unroll
        for (int i = 0; i < 4; i++)
#pragma unroll
            for (int j = 0; j < 4; j++) {
                float sv = s4[i][j] * scaling;
                if (kg0 + j > qg0 + i) sv = -1e9f;
                s4[i][j] = sv;
            }

#pragma unroll
        for (int i = 0; i < 4; i++) {
            float tmax = fmaxf(fmaxf(s4[i][0], s4[i][1]), fmaxf(s4[i][2], s4[i][3]));
#pragma unroll
            for (int msk = 1; msk < 16; msk <<= 1)
                tmax = fmaxf(tmax, __shfl_xor_sync(0xffffffffu, tmax, msk));
            float mn = fmaxf(m[i], tmax);
            float alpha = __expf(m[i] - mn);
            m[i] = mn;
            float rs = 0.0f;
#pragma unroll
            for (int j = 0; j < 4; j++) {
                float p = __expf(s4[i][j] - mn);
                s4[i][j] = p;
                rs += p;
            }
#pragma unroll
            for (int msk = 1; msk < 16; msk <<= 1)
                rs += __shfl_xor_sync(0xffffffffu, rs, msk);
            l[i] = l[i] * alpha + rs;
#pragma unroll
            for (int j = 0; j < 4; j++) o[i][j] *= alpha;
        }

        __syncthreads();
        float* Pt = Kt;
#pragma unroll
        for (int j = 0; j < 4; j++) {
            float4 pv;
            pv.x = s4[0][j]; pv.y = s4[1][j]; pv.z = s4[2][j]; pv.w = s4[3][j];
            *(float4*)&Pt[(tx * 4 + j) * SMS + ty * 4] = pv;
        }
        __syncthreads();

#pragma unroll 4
        for (int c = 0; c < 64; c++) {
            float a[4], bb[4];
            *(float4*)a  = *(const float4*)&Pt[c * SMS + ty * 4];
            *(float4*)bb = *(const float4*)&Vs[c * SMS + tx * 4];
#pragma unroll
            for (int i = 0; i < 4; i++)
#pragma unroll
                for (int j = 0; j < 4; j++)
                    o[i][j] += a[i] * bb[j];
        }
    }

#pragma unroll
    for (int i = 0; i < 4; i++) {
        float inv = 1.0f / l[i];
        float4 v4;
        v4.x = o[i][0] * inv;
        v4.y = o[i][1] * inv;
        v4.z = o[i][2] * inv;
        v4.w = o[i][3] * inv;
        size_t row = ((size_t)b * SS + qi * 64 + ty * 4 + i) * NH + h;
        *(float4*)&ctx[row * DD + tx * 4] = v4;
    }
}

// ---------------- host ----------------
extern "C" void kernel_launch(void* const* d_in, const int* in_sizes, int n_in,
                              void* d_out, int out_size)
{
    const float* hidden = (const float*)d_in[0];
    const float* cosT   = (const float*)d_in[1];
    const float* sinT   = (const float*)d_in[2];
    const float* Wq = (const float*)d_in[4];
    const float* Wk = (const float*)d_in[5];
    const float* Wv = (const float*)d_in[6];
    const float* Wo = (const float*)d_in[7];
    float* out = (float*)d_out;

    float *q, *k, *v, *ctx;
    cudaGetSymbolAddress((void**)&q,   g_q);
    cudaGetSymbolAddress((void**)&k,   g_k);
    cudaGetSymbolAddress((void**)&v,   g_v);
    cudaGetSymbolAddress((void**)&ctx, g_ctx);

    __nv_bfloat16 *hid_h, *hid_l, *w_h, *w_l, *ctx_h, *ctx_l;
    cudaGetSymbolAddress((void**)&hid_h, g_hid_h);
    cudaGetSymbolAddress((void**)&hid_l, g_hid_l);
    cudaGetSymbolAddress((void**)&w_h,   g_w_h);
    cudaGetSymbolAddress((void**)&w_l,   g_w_l);
    cudaGetSymbolAddress((void**)&ctx_h, g_ctx_h);
    cudaGetSymbolAddress((void**)&ctx_l, g_ctx_l);

    const float* Ws[4] = {Wq, Wk, Wv, Wo};

    int n4h = MM * HID / 4;
    split_kernel<<<(n4h + 255) / 256, 256>>>(hidden, hid_h, hid_l, n4h);
    int n4w = HID * HID / 4;
    for (int w = 0; w < 4; w++)
        split_kernel<<<(n4w + 255) / 256, 256>>>(Ws[w], w_h + (size_t)w * HID * HID,
                                                 w_l + (size_t)w * HID * HID, n4w);

    dim3 gGrid(HID / 128, MM / 128);   // (8, 32)

    gemm_bf16_kernel<<<gGrid, 256>>>(hid_h, hid_l,
        w_h + 0 * (size_t)HID * HID, w_l + 0 * (size_t)HID * HID, q);
    gemm_bf16_kernel<<<gGrid, 256>>>(hid_h, hid_l,
        w_h + 1 * (size_t)HID * HID, w_l + 1 * (size_t)HID * HID, k);
    gemm_bf16_kernel<<<gGrid, 256>>>(hid_h, hid_l,
        w_h + 2 * (size_t)HID * HID, w_l + 2 * (size_t)HID * HID, v);

    int nrope = BB * SS * NH * (DD / 2);
    rope_kernel<<<(nrope + 255) / 256, 256>>>(q, k, cosT, sinT);

    int smem = 3 * 64 * SMS * sizeof(float);
    cudaFuncSetAttribute(attn_kernel, cudaFuncAttributeMaxDynamicSharedMemorySize, smem);
    dim3 aGrid(SS / 64, NH, BB);
    attn_kernel<<<aGrid, dim3(16, 16), smem>>>(q, k, v, ctx);

    split_kernel<<<(n4h + 255) / 256, 256>>>(ctx, ctx_h, ctx_l, n4h);
    gemm_bf16_kernel<<<gGrid, 256>>>(ctx_h, ctx_l,
        w_h + 3 * (size_t)HID * HID, w_l + 3 * (size_t)HID * HID, out);
}

// round 4
// speedup vs baseline: 2.5618x; 1.7648x over previous
#include <cuda_runtime.h>
#include <cuda_bf16.h>
#include <cstdint>
#include <math.h>

#define BB 2
#define SS 2048
#define HID 1024
#define NH 16
#define DD 64
#define MM (BB*SS)          // 4096

// ---------------- scratch (no allocation allowed) ----------------
__device__ float g_q[BB*SS*HID];
__device__ float g_k[BB*SS*HID];
__device__ float g_v[BB*SS*HID];
__device__ float g_ctx[BB*SS*HID];

__device__ __nv_bfloat16 g_hid_h[MM*HID];
__device__ __nv_bfloat16 g_hid_l[MM*HID];
__device__ __nv_bfloat16 g_w_h[4][HID*HID];
__device__ __nv_bfloat16 g_w_l[4][HID*HID];
__device__ __nv_bfloat16 g_ctx_h[MM*HID];
__device__ __nv_bfloat16 g_ctx_l[MM*HID];

__device__ __nv_bfloat16 g_qh[MM*HID];
__device__ __nv_bfloat16 g_ql[MM*HID];
__device__ __nv_bfloat16 g_kh[MM*HID];
__device__ __nv_bfloat16 g_kl[MM*HID];
__device__ __nv_bfloat16 g_vh[MM*HID];
__device__ __nv_bfloat16 g_vl[MM*HID];

// ================= helpers =================
__device__ __forceinline__ uint32_t smem_to_u32(const void* smem_ptr) {
    uint32_t addr;
    asm("{ .reg .u64 tmp; cvta.to.shared.u64 tmp, %1; cvt.u32.u64 %0, tmp; }"
        : "=r"(addr) : "l"(smem_ptr));
    return addr;
}
__device__ __forceinline__ void ldm_x4(uint32_t* r, uint32_t addr) {
    asm volatile("ldmatrix.sync.aligned.m8n8.x4.shared.b16 {%0,%1,%2,%3}, [%4];"
        : "=r"(r[0]), "=r"(r[1]), "=r"(r[2]), "=r"(r[3]) : "r"(addr));
}
__device__ __forceinline__ void ldm_x4_t(uint32_t* r, uint32_t addr) {
    asm volatile("ldmatrix.sync.aligned.m8n8.x4.trans.shared.b16 {%0,%1,%2,%3}, [%4];"
        : "=r"(r[0]), "=r"(r[1]), "=r"(r[2]), "=r"(r[3]) : "r"(addr));
}
__device__ __forceinline__ void mma16816(float* c, const uint32_t* a, uint32_t b0, uint32_t b1) {
    asm volatile("mma.sync.aligned.m16n8k16.row.col.f32.bf16.bf16.f32 "
        "{%0,%1,%2,%3}, {%4,%5,%6,%7}, {%8,%9}, {%0,%1,%2,%3};"
        : "+f"(c[0]), "+f"(c[1]), "+f"(c[2]), "+f"(c[3])
        : "r"(a[0]), "r"(a[1]), "r"(a[2]), "r"(a[3]), "r"(b0), "r"(b1));
}
__device__ __forceinline__ void cp16(uint32_t saddr, const void* gaddr) {
    asm volatile("cp.async.cg.shared.global [%0], [%1], 16;" :: "r"(saddr), "l"(gaddr));
}
__device__ __forceinline__ void cp_commit() { asm volatile("cp.async.commit_group;" ::: "memory"); }
__device__ __forceinline__ void cp_wait0() { asm volatile("cp.async.wait_group 0;" ::: "memory"); }
__device__ __forceinline__ void cp_wait1() { asm volatile("cp.async.wait_group 1;" ::: "memory"); }

__device__ __forceinline__ uint32_t pack_bf2(float x, float y) {
    __nv_bfloat162 t = __floats2bfloat162_rn(x, y);
    return *(uint32_t*)&t;
}

// ================= fp32 -> bf16 hi/lo split =================
__global__ void split_kernel(const float* __restrict__ x,
                             __nv_bfloat16* __restrict__ hi,
                             __nv_bfloat16* __restrict__ lo, int n4)
{
    int i = blockIdx.x * blockDim.x + threadIdx.x;
    if (i >= n4) return;
    float4 v = ((const float4*)x)[i];
    float vv[4] = {v.x, v.y, v.z, v.w};
    __nv_bfloat16 h[4], l[4];
#pragma unroll
    for (int j = 0; j < 4; j++) {
        h[j] = __float2bfloat16(vv[j]);
        l[j] = __float2bfloat16(vv[j] - __bfloat162float(h[j]));
    }
    __nv_bfloat162* hp = (__nv_bfloat162*)hi;
    __nv_bfloat162* lp = (__nv_bfloat162*)lo;
    hp[i * 2 + 0] = __nv_bfloat162(h[0], h[1]);
    hp[i * 2 + 1] = __nv_bfloat162(h[2], h[3]);
    lp[i * 2 + 0] = __nv_bfloat162(l[0], l[1]);
    lp[i * 2 + 1] = __nv_bfloat162(l[2], l[3]);
}

// ================= HMMA GEMM (unchanged from R3) =================
#define KC 32
#define NITER (HID / KC)
#define SROW 80
#define SBUF (128 * SROW)

__global__ __launch_bounds__(256, 1) void gemm_bf16_kernel(
    const __nv_bfloat16* __restrict__ Ah, const __nv_bfloat16* __restrict__ Al,
    const __nv_bfloat16* __restrict__ Bh, const __nv_bfloat16* __restrict__ Bl,
    float* __restrict__ C)
{
    __shared__ __align__(16) unsigned char smem[4 * SBUF];

    const int tid  = threadIdx.x;
    const int wid  = tid >> 5;
    const int lane = tid & 31;
    const int wm   = wid >> 2;
    const int wn   = wid & 3;
    const int m0   = blockIdx.y * 128;
    const int n0   = blockIdx.x * 128;

    const uint32_t sb = smem_to_u32(smem);
    const uint32_t sA  = sb;
    const uint32_t sAl = sb + SBUF;
    const uint32_t sB  = sb + 2 * SBUF;
    const uint32_t sBl = sb + 3 * SBUF;

    const int rowA  = lane & 15;
    const int kofsA = (lane >> 4) * 16;
    const int rowB  = (lane & 7) + ((lane >> 4) & 1) * 8;
    const int kofsB = ((lane >> 3) & 1) * 16;

    float acc[4][4][4];
#pragma unroll
    for (int i = 0; i < 4; i++)
#pragma unroll
        for (int j = 0; j < 4; j++)
#pragma unroll
            for (int r = 0; r < 4; r++) acc[i][j][r] = 0.0f;

    uint4 stA[2], stAl[2], stB[2], stBl[2];
    const int row_s = tid >> 2;
    const int kc_s  = tid & 3;

#pragma unroll
    for (int i = 0; i < 2; i++) {
        int row = row_s + i * 64;
        size_t ga = (size_t)(m0 + row) * HID + kc_s * 8;
        size_t gb = (size_t)(n0 + row) * HID + kc_s * 8;
        stA[i]  = *(const uint4*)(Ah + ga);
        stAl[i] = *(const uint4*)(Al + ga);
        stB[i]  = *(const uint4*)(Bh + gb);
        stBl[i] = *(const uint4*)(Bl + gb);
    }

    for (int it = 0; it < NITER; it++) {
        __syncthreads();
#pragma unroll
        for (int i = 0; i < 2; i++) {
            int row = row_s + i * 64;
            int off = row * SROW + kc_s * 16;
            *(uint4*)(smem + off)            = stA[i];
            *(uint4*)(smem + SBUF + off)     = stAl[i];
            *(uint4*)(smem + 2 * SBUF + off) = stB[i];
            *(uint4*)(smem + 3 * SBUF + off) = stBl[i];
        }
        __syncthreads();

        if (it + 1 < NITER) {
            int k0 = (it + 1) * KC;
#pragma unroll
            for (int i = 0; i < 2; i++) {
                int row = row_s + i * 64;
                size_t ga = (size_t)(m0 + row) * HID + k0 + kc_s * 8;
                size_t gb = (size_t)(n0 + row) * HID + k0 + kc_s * 8;
                stA[i]  = *(const uint4*)(Ah + ga);
                stAl[i] = *(const uint4*)(Al + ga);
                stB[i]  = *(const uint4*)(Bh + gb);
                stBl[i] = *(const uint4*)(Bl + gb);
            }
        }

#pragma unroll
        for (int kk = 0; kk < 2; kk++) {
            const int kb = kk * 32;
            uint32_t ah[4][4], bh[4][2];
#pragma unroll
            for (int mt = 0; mt < 4; mt++) {
                uint32_t addr = sA + (wm * 64 + mt * 16 + rowA) * SROW + kb + kofsA;
                ldm_x4(ah[mt], addr);
            }
#pragma unroll
            for (int nt2 = 0; nt2 < 2; nt2++) {
                uint32_t t[4];
                uint32_t addr = sB + (wn * 32 + nt2 * 16 + rowB) * SROW + kb + kofsB;
                ldm_x4(t, addr);
                bh[nt2 * 2 + 0][0] = t[0]; bh[nt2 * 2 + 0][1] = t[1];
                bh[nt2 * 2 + 1][0] = t[2]; bh[nt2 * 2 + 1][1] = t[3];
            }
#pragma unroll
            for (int mt = 0; mt < 4; mt++)
#pragma unroll
                for (int nt = 0; nt < 4; nt++)
                    mma16816(acc[mt][nt], ah[mt], bh[nt][0], bh[nt][1]);
            {
                uint32_t bl[4][2];
#pragma unroll
                for (int nt2 = 0; nt2 < 2; nt2++) {
                    uint32_t t[4];
                    uint32_t addr = sBl + (wn * 32 + nt2 * 16 + rowB) * SROW + kb + kofsB;
                    ldm_x4(t, addr);
                    bl[nt2 * 2 + 0][0] = t[0]; bl[nt2 * 2 + 0][1] = t[1];
                    bl[nt2 * 2 + 1][0] = t[2]; bl[nt2 * 2 + 1][1] = t[3];
                }
#pragma unroll
                for (int mt = 0; mt < 4; mt++)
#pragma unroll
                    for (int nt = 0; nt < 4; nt++)
                        mma16816(acc[mt][nt], ah[mt], bl[nt][0], bl[nt][1]);
            }
            {
                uint32_t al[4][4];
#pragma unroll
                for (int mt = 0; mt < 4; mt++) {
                    uint32_t addr = sAl + (wm * 64 + mt * 16 + rowA) * SROW + kb + kofsA;
                    ldm_x4(al[mt], addr);
                }
#pragma unroll
                for (int mt = 0; mt < 4; mt++)
#pragma unroll
                    for (int nt = 0; nt < 4; nt++)
                        mma16816(acc[mt][nt], al[mt], bh[nt][0], bh[nt][1]);
            }
        }
    }

    const int rr = lane >> 2;
    const int cc = (lane & 3) * 2;
#pragma unroll
    for (int mt = 0; mt < 4; mt++) {
#pragma unroll
        for (int nt = 0; nt < 4; nt++) {
            int r = m0 + wm * 64 + mt * 16 + rr;
            int c = n0 + wn * 32 + nt * 8 + cc;
            float2 v0 = make_float2(acc[mt][nt][0], acc[mt][nt][1]);
            float2 v1 = make_float2(acc[mt][nt][2], acc[mt][nt][3]);
            *(float2*)&C[(size_t)r * HID + c]       = v0;
            *(float2*)&C[(size_t)(r + 8) * HID + c] = v1;
        }
    }
}

// ---------------- RoPE + split (q scaled by 1/8, exact) ----------------
__global__ void rope_split_kernel(const float* __restrict__ q, const float* __restrict__ k,
                                  const float* __restrict__ cosT, const float* __restrict__ sinT,
                                  __nv_bfloat16* __restrict__ qh, __nv_bfloat16* __restrict__ ql,
                                  __nv_bfloat16* __restrict__ kh, __nv_bfloat16* __restrict__ kl)
{
    int idx = blockIdx.x * blockDim.x + threadIdx.x;   // over B*S*H*32 pairs
    if (idx >= BB * SS * NH * (DD / 2)) return;
    int p = idx & 31;
    int s = (idx >> 9) & (SS - 1);
    float c  = cosT[s * 32 + p];
    float sn = sinT[s * 32 + p];
    int base = idx * 2;

    float a = q[base], b = q[base + 1];
    float r0 = (a * c - b * sn) * 0.125f;
    float r1 = (a * sn + b * c) * 0.125f;
    __nv_bfloat16 h0 = __float2bfloat16(r0), h1 = __float2bfloat16(r1);
    qh[base] = h0; qh[base + 1] = h1;
    ql[base]     = __float2bfloat16(r0 - __bfloat162float(h0));
    ql[base + 1] = __float2bfloat16(r1 - __bfloat162float(h1));

    a = k[base]; b = k[base + 1];
    r0 = a * c - b * sn;
    r1 = a * sn + b * c;
    h0 = __float2bfloat16(r0); h1 = __float2bfloat16(r1);
    kh[base] = h0; kh[base + 1] = h1;
    kl[base]     = __float2bfloat16(r0 - __bfloat162float(h0));
    kl[base + 1] = __float2bfloat16(r1 - __bfloat162float(h1));
}

// ---------------- HMMA flash attention (causal) ----------------
// CTA: 128 q-rows x one (b,h). 8 warps x 16 rows. KV tiles of 64, double-buffered cp.async.
#define ASTR 144                 // bytes per bf16 row of 64 (+8 pad)
#define AQB  (128 * ASTR)        // 18432, one Q buffer
#define AKB  (64 * ASTR)         // 9216, one K/V operand tile
#define AKVSTG (4 * AKB)         // Kh,Kl,Vh,Vl per stage = 36864
#define ATTN_SMEM (2 * AQB + 2 * AKVSTG)   // 110592

__global__ __launch_bounds__(256, 2) void attn_hmma_kernel(
    const __nv_bfloat16* __restrict__ qh, const __nv_bfloat16* __restrict__ ql,
    const __nv_bfloat16* __restrict__ kh, const __nv_bfloat16* __restrict__ kl,
    const __nv_bfloat16* __restrict__ vh, const __nv_bfloat16* __restrict__ vl,
    float* __restrict__ ctx)
{
    extern __shared__ unsigned char sm[];
    const int qi  = blockIdx.x;
    const int h   = blockIdx.y;
    const int b   = blockIdx.z;
    const int tid = threadIdx.x;
    const int wid = tid >> 5;
    const int lane = tid & 31;
    const int q0  = qi * 128;

    const uint32_t sb  = smem_to_u32(sm);
    const uint32_t sQh = sb;
    const uint32_t sQl = sb + AQB;
    const uint32_t sKV = sb + 2 * AQB;

    const int ntiles = 2 * qi + 2;

    // ---- prologue: Q + KV tile0 via cp.async ----
    {
        int row = tid >> 1;              // 0..127
        int c   = (tid & 1) * 4;         // two 4-chunk halves
        size_t g = ((size_t)(b * SS + q0 + row) * NH + h) * DD;
#pragma unroll
        for (int j = 0; j < 4; j++) {
            cp16(sQh + row * ASTR + (c + j) * 16, qh + g + (c + j) * 8);
            cp16(sQl + row * ASTR + (c + j) * 16, ql + g + (c + j) * 8);
        }
    }
    // KV loader: 64 rows x 8 chunks per operand; 256 threads -> 2 chunks each per operand
    auto loadKV = [&](int jt, int buf) {
        uint32_t base = sKV + buf * AKVSTG;
        int row = tid >> 2;              // 0..63
        int c   = (tid & 3) * 2;         // 2 chunks
        size_t g = ((size_t)(b * SS + jt * 64 + row) * NH + h) * DD;
#pragma unroll
        for (int j = 0; j < 2; j++) {
            uint32_t so = row * ASTR + (c + j) * 16;
            size_t go = g + (c + j) * 8;
            cp16(base + 0 * AKB + so, kh + go);
            cp16(base + 1 * AKB + so, kl + go);
            cp16(base + 2 * AKB + so, vh + go);
            cp16(base + 3 * AKB + so, vl + go);
        }
    };
    loadKV(0, 0);
    cp_commit();
    if (ntiles > 1) { loadKV(1, 1); cp_commit(); cp_wait1(); }
    else cp_wait0();
    __syncthreads();

    // ---- state ----
    float mrow[2] = {-1e30f, -1e30f};
    float lrow[2] = {0.0f, 0.0f};
    float oacc[8][4];
#pragma unroll
    for (int nt = 0; nt < 8; nt++)
#pragma unroll
        for (int r = 0; r < 4; r++) oacc[nt][r] = 0.0f;

    const int rowA  = lane & 15;
    const int kofsA = (lane >> 4) * 16;
    const int rowB  = (lane & 7) + ((lane >> 4) & 1) * 8;
    const int kofsB = ((lane >> 3) & 1) * 16;

    for (int jt = 0; jt < ntiles; jt++) {
        const int cur = jt & 1;
        const uint32_t bK  = sKV + cur * AKVSTG;
        const uint32_t bKl = bK + AKB;
        const uint32_t bV  = bK + 2 * AKB;
        const uint32_t bVl = bK + 3 * AKB;

        // ---- scores = Q K^T (3-term split), 128x64 per CTA, warp: 16 rows ----
        float sc[8][4];
#pragma unroll
        for (int nt = 0; nt < 8; nt++)
#pragma unroll
            for (int r = 0; r < 4; r++) sc[nt][r] = 0.0f;

#pragma unroll
        for (int ks = 0; ks < 4; ks++) {
            uint32_t ah[4], al[4];
            uint32_t aoff = (wid * 16 + rowA) * ASTR + ks * 32 + kofsA;
            ldm_x4(ah, sQh + aoff);
            ldm_x4(al, sQl + aoff);
#pragma unroll
            for (int nt2 = 0; nt2 < 4; nt2++) {
                uint32_t bh4[4], bl4[4];
                uint32_t boff = (nt2 * 16 + rowB) * ASTR + ks * 32 + kofsB;
                ldm_x4(bh4, bK + boff);
                ldm_x4(bl4, bKl + boff);
                mma16816(sc[2 * nt2],     ah, bh4[0], bh4[1]);
                mma16816(sc[2 * nt2 + 1], ah, bh4[2], bh4[3]);
                mma16816(sc[2 * nt2],     ah, bl4[0], bl4[1]);
                mma16816(sc[2 * nt2 + 1], ah, bl4[2], bl4[3]);
                mma16816(sc[2 * nt2],     al, bh4[0], bh4[1]);
                mma16816(sc[2 * nt2 + 1], al, bh4[2], bh4[3]);
            }
        }

        // ---- causal mask (scale already folded into q) ----
        const int kv0 = jt * 64;
        if (kv0 + 63 > q0 + wid * 16) {
            const int qr = q0 + wid * 16 + (lane >> 2);
#pragma unroll
            for (int nt = 0; nt < 8; nt++) {
#pragma unroll
                for (int r = 0; r < 4; r++) {
                    int qrow = qr + ((r >= 2) ? 8 : 0);
                    int kvc  = kv0 + nt * 8 + (lane & 3) * 2 + (r & 1);
                    if (kvc > qrow) sc[nt][r] = -1e30f;
                }
            }
        }

        // ---- online softmax (rows r, r+8 per thread) ----
#pragma unroll
        for (int rh = 0; rh < 2; rh++) {
            float mx = -1e30f;
#pragma unroll
            for (int nt = 0; nt < 8; nt++)
                mx = fmaxf(mx, fmaxf(sc[nt][rh * 2], sc[nt][rh * 2 + 1]));
            mx = fmaxf(mx, __shfl_xor_sync(0xffffffffu, mx, 1));
            mx = fmaxf(mx, __shfl_xor_sync(0xffffffffu, mx, 2));
            float mn = fmaxf(mrow[rh], mx);
            float alpha = __expf(mrow[rh] - mn);
            mrow[rh] = mn;
            float sum = 0.0f;
#pragma unroll
            for (int nt = 0; nt < 8; nt++) {
                float p0 = __expf(sc[nt][rh * 2]     - mn);
                float p1 = __expf(sc[nt][rh * 2 + 1] - mn);
                sc[nt][rh * 2]     = p0;
                sc[nt][rh * 2 + 1] = p1;
                sum += p0 + p1;
            }
            sum += __shfl_xor_sync(0xffffffffu, sum, 1);
            sum += __shfl_xor_sync(0xffffffffu, sum, 2);
            lrow[rh] = lrow[rh] * alpha + sum;
#pragma unroll
            for (int nt = 0; nt < 8; nt++) {
                oacc[nt][rh * 2]     *= alpha;
                oacc[nt][rh * 2 + 1] *= alpha;
            }
        }

        // ---- build P fragments (in-register, hi/lo) ----
        uint32_t ph[4][4], pl[4][4];
#pragma unroll
        for (int ks2 = 0; ks2 < 4; ks2++) {
            const int na = 2 * ks2, nb = 2 * ks2 + 1;
            float pv[4][2] = {{sc[na][0], sc[na][1]}, {sc[na][2], sc[na][3]},
                              {sc[nb][0], sc[nb][1]}, {sc[nb][2], sc[nb][3]}};
#pragma unroll
            for (int a = 0; a < 4; a++) {
                __nv_bfloat16 h0 = __float2bfloat16(pv[a][0]);
                __nv_bfloat16 h1 = __float2bfloat16(pv[a][1]);
                ph[ks2][a] = ((uint32_t)*(uint16_t*)&h1 << 16) | *(uint16_t*)&h0;
                __nv_bfloat16 l0 = __float2bfloat16(pv[a][0] - __bfloat162float(h0));
                __nv_bfloat16 l1 = __float2bfloat16(pv[a][1] - __bfloat162float(h1));
                pl[ks2][a] = ((uint32_t)*(uint16_t*)&l1 << 16) | *(uint16_t*)&l0;
            }
        }

        // ---- O += P V (3-term split) ----
#pragma unroll
        for (int ks2 = 0; ks2 < 4; ks2++) {
#pragma unroll
            for (int nt2 = 0; nt2 < 4; nt2++) {
                uint32_t bvh[4], bvl[4];
                uint32_t voff = (ks2 * 16 + (lane & 15)) * ASTR + (nt2 * 16 + (lane >> 4) * 8) * 2;
                ldm_x4_t(bvh, bV + voff);
                ldm_x4_t(bvl, bVl + voff);
                mma16816(oacc[2 * nt2],     ph[ks2], bvh[0], bvh[1]);
                mma16816(oacc[2 * nt2 + 1], ph[ks2], bvh[2], bvh[3]);
                mma16816(oacc[2 * nt2],     ph[ks2], bvl[0], bvl[1]);
                mma16816(oacc[2 * nt2 + 1], ph[ks2], bvl[2], bvl[3]);
                mma16816(oacc[2 * nt2],     pl[ks2], bvh[0], bvh[1]);
                mma16816(oacc[2 * nt2 + 1], pl[ks2], bvh[2], bvh[3]);
            }
        }

        // ---- pipeline advance ----
        if (jt + 1 < ntiles) {
            __syncthreads();
            if (jt + 2 < ntiles) { loadKV(jt + 2, cur); cp_commit(); cp_wait1(); }
            else cp_wait0();
            __syncthreads();
        }
    }

    // ---- epilogue ----
#pragma unroll
    for (int rh = 0; rh < 2; rh++) {
        float inv = 1.0f / lrow[rh];
        int row = q0 + wid * 16 + (lane >> 2) + rh * 8;
        float* crow = ctx + ((size_t)(b * SS + row) * NH + h) * DD;
#pragma unroll
        for (int nt = 0; nt < 8; nt++) {
            float2 v = make_float2(oacc[nt][rh * 2] * inv, oacc[nt][rh * 2 + 1] * inv);
            *(float2*)&crow[nt * 8 + (lane & 3) * 2] = v;
        }
    }
}

// ---------------- host ----------------
extern "C" void kernel_launch(void* const* d_in, const int* in_sizes, int n_in,
                              void* d_out, int out_size)
{
    const float* hidden = (const float*)d_in[0];
    const float* cosT   = (const float*)d_in[1];
    const float* sinT   = (const float*)d_in[2];
    const float* Wq = (const float*)d_in[4];
    const float* Wk = (const float*)d_in[5];
    const float* Wv = (const float*)d_in[6];
    const float* Wo = (const float*)d_in[7];
    float* out = (float*)d_out;

    float *q, *k, *v, *ctx;
    cudaGetSymbolAddress((void**)&q,   g_q);
    cudaGetSymbolAddress((void**)&k,   g_k);
    cudaGetSymbolAddress((void**)&v,   g_v);
    cudaGetSymbolAddress((void**)&ctx, g_ctx);

    __nv_bfloat16 *hid_h, *hid_l, *w_h, *w_l, *ctx_h, *ctx_l;
    __nv_bfloat16 *qh, *ql, *kh, *kl, *vh, *vl;
    cudaGetSymbolAddress((void**)&hid_h, g_hid_h);
    cudaGetSymbolAddress((void**)&hid_l, g_hid_l);
    cudaGetSymbolAddress((void**)&w_h,   g_w_h);
    cudaGetSymbolAddress((void**)&w_l,   g_w_l);
    cudaGetSymbolAddress((void**)&ctx_h, g_ctx_h);
    cudaGetSymbolAddress((void**)&ctx_l, g_ctx_l);
    cudaGetSymbolAddress((void**)&qh, g_qh);
    cudaGetSymbolAddress((void**)&ql, g_ql);
    cudaGetSymbolAddress((void**)&kh, g_kh);
    cudaGetSymbolAddress((void**)&kl, g_kl);
    cudaGetSymbolAddress((void**)&vh, g_vh);
    cudaGetSymbolAddress((void**)&vl, g_vl);

    const float* Ws[4] = {Wq, Wk, Wv, Wo};

    int n4h = MM * HID / 4;
    split_kernel<<<(n4h + 255) / 256, 256>>>(hidden, hid_h, hid_l, n4h);
    int n4w = HID * HID / 4;
    for (int w = 0; w < 4; w++)
        split_kernel<<<(n4w + 255) / 256, 256>>>(Ws[w], w_h + (size_t)w * HID * HID,
                                                 w_l + (size_t)w * HID * HID, n4w);

    dim3 gGrid(HID / 128, MM / 128);

    gemm_bf16_kernel<<<gGrid, 256>>>(hid_h, hid_l,
        w_h + 0 * (size_t)HID * HID, w_l + 0 * (size_t)HID * HID, q);
    gemm_bf16_kernel<<<gGrid, 256>>>(hid_h, hid_l,
        w_h + 1 * (size_t)HID * HID, w_l + 1 * (size_t)HID * HID, k);
    gemm_bf16_kernel<<<gGrid, 256>>>(hid_h, hid_l,
        w_h + 2 * (size_t)HID * HID, w_l + 2 * (size_t)HID * HID, v);

    int nrope = BB * SS * NH * (DD / 2);
    rope_split_kernel<<<(nrope + 255) / 256, 256>>>(q, k, cosT, sinT, qh, ql, kh, kl);
    split_kernel<<<(n4h + 255) / 256, 256>>>(v, vh, vl, n4h);

    cudaFuncSetAttribute(attn_hmma_kernel, cudaFuncAttributeMaxDynamicSharedMemorySize, ATTN_SMEM);
    dim3 aGrid(SS / 128, NH, BB);   // (16, 16, 2)
    attn_hmma_kernel<<<aGrid, 256, ATTN_SMEM>>>(qh, ql, kh, kl, vh, vl, ctx);

    split_kernel<<<(n4h + 255) / 256, 256>>>(ctx, ctx_h, ctx_l, n4h);
    gemm_bf16_kernel<<<gGrid, 256>>>(ctx_h, ctx_l,
        w_h + 3 * (size_t)HID * HID, w_l + 3 * (size_t)HID * HID, out);
}

// round 5
// speedup vs baseline: 2.6407x; 1.0308x over previous
#include <cuda_runtime.h>
#include <cuda_bf16.h>
#include <cstdint>
#include <math.h>

#define BB 2
#define SS 2048
#define HID 1024
#define NH 16
#define DD 64
#define MM (BB*SS)          // 4096

// ---------------- scratch (no allocation allowed) ----------------
__device__ float g_q[BB*SS*HID];
__device__ float g_k[BB*SS*HID];

__device__ __nv_bfloat16 g_hid_h[MM*HID];
__device__ __nv_bfloat16 g_hid_l[MM*HID];
__device__ __nv_bfloat16 g_w_h[4][HID*HID];
__device__ __nv_bfloat16 g_w_l[4][HID*HID];
__device__ __nv_bfloat16 g_ctx_h[MM*HID];
__device__ __nv_bfloat16 g_ctx_l[MM*HID];

__device__ __nv_bfloat16 g_qh[MM*HID];
__device__ __nv_bfloat16 g_ql[MM*HID];
__device__ __nv_bfloat16 g_kh[MM*HID];
__device__ __nv_bfloat16 g_kl[MM*HID];
__device__ __nv_bfloat16 g_vh[MM*HID];
__device__ __nv_bfloat16 g_vl[MM*HID];

// ================= helpers =================
__device__ __forceinline__ uint32_t smem_to_u32(const void* smem_ptr) {
    uint32_t addr;
    asm("{ .reg .u64 tmp; cvta.to.shared.u64 tmp, %1; cvt.u32.u64 %0, tmp; }"
        : "=r"(addr) : "l"(smem_ptr));
    return addr;
}
__device__ __forceinline__ void ldm_x4(uint32_t* r, uint32_t addr) {
    asm volatile("ldmatrix.sync.aligned.m8n8.x4.shared.b16 {%0,%1,%2,%3}, [%4];"
        : "=r"(r[0]), "=r"(r[1]), "=r"(r[2]), "=r"(r[3]) : "r"(addr));
}
__device__ __forceinline__ void ldm_x4_t(uint32_t* r, uint32_t addr) {
    asm volatile("ldmatrix.sync.aligned.m8n8.x4.trans.shared.b16 {%0,%1,%2,%3}, [%4];"
        : "=r"(r[0]), "=r"(r[1]), "=r"(r[2]), "=r"(r[3]) : "r"(addr));
}
__device__ __forceinline__ void mma16816(float* c, const uint32_t* a, uint32_t b0, uint32_t b1) {
    asm volatile("mma.sync.aligned.m16n8k16.row.col.f32.bf16.bf16.f32 "
        "{%0,%1,%2,%3}, {%4,%5,%6,%7}, {%8,%9}, {%0,%1,%2,%3};"
        : "+f"(c[0]), "+f"(c[1]), "+f"(c[2]), "+f"(c[3])
        : "r"(a[0]), "r"(a[1]), "r"(a[2]), "r"(a[3]), "r"(b0), "r"(b1));
}
__device__ __forceinline__ void cp16(uint32_t saddr, const void* gaddr) {
    asm volatile("cp.async.cg.shared.global [%0], [%1], 16;" :: "r"(saddr), "l"(gaddr));
}
__device__ __forceinline__ void cp_commit() { asm volatile("cp.async.commit_group;" ::: "memory"); }
__device__ __forceinline__ void cp_wait0() { asm volatile("cp.async.wait_group 0;" ::: "memory"); }
__device__ __forceinline__ void cp_wait1() { asm volatile("cp.async.wait_group 1;" ::: "memory"); }

// ================= fp32 -> bf16 hi/lo split =================
__global__ void split_kernel(const float* __restrict__ x,
                             __nv_bfloat16* __restrict__ hi,
                             __nv_bfloat16* __restrict__ lo, int n4)
{
    int i = blockIdx.x * blockDim.x + threadIdx.x;
    if (i >= n4) return;
    float4 v = ((const float4*)x)[i];
    float vv[4] = {v.x, v.y, v.z, v.w};
    __nv_bfloat16 h[4], l[4];
#pragma unroll
    for (int j = 0; j < 4; j++) {
        h[j] = __float2bfloat16(vv[j]);
        l[j] = __float2bfloat16(vv[j] - __bfloat162float(h[j]));
    }
    __nv_bfloat162* hp = (__nv_bfloat162*)hi;
    __nv_bfloat162* lp = (__nv_bfloat162*)lo;
    hp[i * 2 + 0] = __nv_bfloat162(h[0], h[1]);
    hp[i * 2 + 1] = __nv_bfloat162(h[2], h[3]);
    lp[i * 2 + 0] = __nv_bfloat162(l[0], l[1]);
    lp[i * 2 + 1] = __nv_bfloat162(l[2], l[3]);
}

// ================= pipelined HMMA GEMM, tile 128x64 =================
// C[M=4096][64-slice of 1024] = A @ W^T, split bf16 3-term.
// 8 warps (2m x 4n), warp tile 64x16. cp.async 2-stage, 1 sync/iter.
// z selects weight/output: z0 -> f32 c0, z1 -> f32 c1, z2 -> split vh/vl.
#define GROW 80                 // smem row stride bytes (32 bf16 + pad)
#define GA_B (128 * GROW)       // 10240 per A array
#define GB_B (64 * GROW)        // 5120 per B array
#define GSTG (2 * GA_B + 2 * GB_B)  // 30720 per stage
#define GNIT (HID / 32)         // 32 iters

__global__ __launch_bounds__(256, 2) void gemm_pipe_kernel(
    const __nv_bfloat16* __restrict__ Ah, const __nv_bfloat16* __restrict__ Al,
    const __nv_bfloat16* __restrict__ W0h, const __nv_bfloat16* __restrict__ W0l,
    const __nv_bfloat16* __restrict__ W1h, const __nv_bfloat16* __restrict__ W1l,
    const __nv_bfloat16* __restrict__ W2h, const __nv_bfloat16* __restrict__ W2l,
    float* __restrict__ c0, float* __restrict__ c1,
    __nv_bfloat16* __restrict__ vh, __nv_bfloat16* __restrict__ vl)
{
    __shared__ __align__(16) unsigned char smem[2 * GSTG];

    const int tid  = threadIdx.x;
    const int wid  = tid >> 5;
    const int lane = tid & 31;
    const int wm   = wid >> 2;      // 0..1
    const int wn   = wid & 3;       // 0..3
    const int n0   = blockIdx.x * 64;
    const int m0   = blockIdx.y * 128;
    const int z    = blockIdx.z;

    const __nv_bfloat16* Bh = (z == 0) ? W0h : (z == 1) ? W1h : W2h;
    const __nv_bfloat16* Bl = (z == 0) ? W0l : (z == 1) ? W1l : W2l;

    const uint32_t sb = smem_to_u32(smem);

    // loader indices
    const int rL = tid >> 2;        // 0..63
    const int cL = tid & 3;         // 0..3 (16B chunks)

    auto load_stage = [&](int it, int buf) {
        const int k0 = it * 32;
        uint32_t st = sb + buf * GSTG;
        // A: 128 rows (two halves), arrays Ah, Al
#pragma unroll
        for (int half = 0; half < 2; half++) {
            int row = rL + half * 64;
            size_t g = (size_t)(m0 + row) * HID + k0 + cL * 8;
            uint32_t so = row * GROW + cL * 16;
            cp16(st + so,        Ah + g);
            cp16(st + GA_B + so, Al + g);
        }
        // B: 64 rows, arrays Bh, Bl
        {
            size_t g = (size_t)(n0 + rL) * HID + k0 + cL * 8;
            uint32_t so = rL * GROW + cL * 16;
            cp16(st + 2 * GA_B + so,        Bh + g);
            cp16(st + 2 * GA_B + GB_B + so, Bl + g);
        }
    };

    float acc[4][2][4];
#pragma unroll
    for (int i = 0; i < 4; i++)
#pragma unroll
        for (int j = 0; j < 2; j++)
#pragma unroll
            for (int r = 0; r < 4; r++) acc[i][j][r] = 0.0f;

    const int rowA  = lane & 15;
    const int kofsA = (lane >> 4) * 16;
    const int rowB  = (lane & 7) + ((lane >> 4) & 1) * 8;
    const int kofsB = ((lane >> 3) & 1) * 16;

    load_stage(0, 0);
    cp_commit();

    for (int it = 0; it < GNIT; it++) {
        const int cur = it & 1;
        cp_wait0();
        __syncthreads();
        if (it + 1 < GNIT) { load_stage(it + 1, cur ^ 1); cp_commit(); }

        const uint32_t sA  = sb + cur * GSTG;
        const uint32_t sAl = sA + GA_B;
        const uint32_t sB  = sA + 2 * GA_B;
        const uint32_t sBl = sB + GB_B;

#pragma unroll
        for (int kk = 0; kk < 2; kk++) {
            const int kb = kk * 32;
            uint32_t ah[4][4], bh4[4], bl4[4];
#pragma unroll
            for (int mt = 0; mt < 4; mt++)
                ldm_x4(ah[mt], sA + (wm * 64 + mt * 16 + rowA) * GROW + kb + kofsA);
            ldm_x4(bh4, sB  + (wn * 16 + rowB) * GROW + kb + kofsB);
            ldm_x4(bl4, sBl + (wn * 16 + rowB) * GROW + kb + kofsB);
#pragma unroll
            for (int mt = 0; mt < 4; mt++) {
                mma16816(acc[mt][0], ah[mt], bh4[0], bh4[1]);
                mma16816(acc[mt][1], ah[mt], bh4[2], bh4[3]);
                mma16816(acc[mt][0], ah[mt], bl4[0], bl4[1]);
                mma16816(acc[mt][1], ah[mt], bl4[2], bl4[3]);
            }
            uint32_t al[4];
#pragma unroll
            for (int mt = 0; mt < 4; mt++) {
                ldm_x4(al, sAl + (wm * 64 + mt * 16 + rowA) * GROW + kb + kofsA);
                mma16816(acc[mt][0], al, bh4[0], bh4[1]);
                mma16816(acc[mt][1], al, bh4[2], bh4[3]);
            }
        }
        __syncthreads();
    }

    // epilogue
    const int rr = lane >> 2;
    const int cc = (lane & 3) * 2;
    if (z == 2) {
#pragma unroll
        for (int mt = 0; mt < 4; mt++) {
#pragma unroll
            for (int nt = 0; nt < 2; nt++) {
                int r = m0 + wm * 64 + mt * 16 + rr;
                int c = n0 + wn * 16 + nt * 8 + cc;
#pragma unroll
                for (int half = 0; half < 2; half++) {
                    float x0 = acc[mt][nt][half * 2 + 0];
                    float x1 = acc[mt][nt][half * 2 + 1];
                    size_t idx = (size_t)(r + half * 8) * HID + c;
                    __nv_bfloat16 h0 = __float2bfloat16(x0);
                    __nv_bfloat16 h1 = __float2bfloat16(x1);
                    __nv_bfloat16 l0 = __float2bfloat16(x0 - __bfloat162float(h0));
                    __nv_bfloat16 l1 = __float2bfloat16(x1 - __bfloat162float(h1));
                    *(__nv_bfloat162*)&vh[idx] = __nv_bfloat162(h0, h1);
                    *(__nv_bfloat162*)&vl[idx] = __nv_bfloat162(l0, l1);
                }
            }
        }
    } else {
        float* C = (z == 0) ? c0 : c1;
#pragma unroll
        for (int mt = 0; mt < 4; mt++) {
#pragma unroll
            for (int nt = 0; nt < 2; nt++) {
                int r = m0 + wm * 64 + mt * 16 + rr;
                int c = n0 + wn * 16 + nt * 8 + cc;
                *(float2*)&C[(size_t)r * HID + c] =
                    make_float2(acc[mt][nt][0], acc[mt][nt][1]);
                *(float2*)&C[(size_t)(r + 8) * HID + c] =
                    make_float2(acc[mt][nt][2], acc[mt][nt][3]);
            }
        }
    }
}

// ---------------- RoPE + split (q scaled by 1/8, exact) ----------------
__global__ void rope_split_kernel(const float* __restrict__ q, const float* __restrict__ k,
                                  const float* __restrict__ cosT, const float* __restrict__ sinT,
                                  __nv_bfloat16* __restrict__ qh, __nv_bfloat16* __restrict__ ql,
                                  __nv_bfloat16* __restrict__ kh, __nv_bfloat16* __restrict__ kl)
{
    int idx = blockIdx.x * blockDim.x + threadIdx.x;
    if (idx >= BB * SS * NH * (DD / 2)) return;
    int p = idx & 31;
    int s = (idx >> 9) & (SS - 1);
    float c  = cosT[s * 32 + p];
    float sn = sinT[s * 32 + p];
    int base = idx * 2;

    float a = q[base], b = q[base + 1];
    float r0 = (a * c - b * sn) * 0.125f;
    float r1 = (a * sn + b * c) * 0.125f;
    __nv_bfloat16 h0 = __float2bfloat16(r0), h1 = __float2bfloat16(r1);
    qh[base] = h0; qh[base + 1] = h1;
    ql[base]     = __float2bfloat16(r0 - __bfloat162float(h0));
    ql[base + 1] = __float2bfloat16(r1 - __bfloat162float(h1));

    a = k[base]; b = k[base + 1];
    r0 = a * c - b * sn;
    r1 = a * sn + b * c;
    h0 = __float2bfloat16(r0); h1 = __float2bfloat16(r1);
    kh[base] = h0; kh[base + 1] = h1;
    kl[base]     = __float2bfloat16(r0 - __bfloat162float(h0));
    kl[base + 1] = __float2bfloat16(r1 - __bfloat162float(h1));
}

// ---------------- HMMA flash attention (causal) ----------------
#define ASTR 144
#define AQB  (128 * ASTR)
#define AKB  (64 * ASTR)
#define AKVSTG (4 * AKB)
#define ATTN_SMEM (2 * AQB + 2 * AKVSTG)

__global__ __launch_bounds__(256, 2) void attn_hmma_kernel(
    const __nv_bfloat16* __restrict__ qh, const __nv_bfloat16* __restrict__ ql,
    const __nv_bfloat16* __restrict__ kh, const __nv_bfloat16* __restrict__ kl,
    const __nv_bfloat16* __restrict__ vh, const __nv_bfloat16* __restrict__ vl,
    __nv_bfloat16* __restrict__ ctxh, __nv_bfloat16* __restrict__ ctxl)
{
    extern __shared__ unsigned char sm[];
    const int qi  = blockIdx.x;
    const int h   = blockIdx.y;
    const int b   = blockIdx.z;
    const int tid = threadIdx.x;
    const int wid = tid >> 5;
    const int lane = tid & 31;
    const int q0  = qi * 128;

    const uint32_t sb  = smem_to_u32(sm);
    const uint32_t sQh = sb;
    const uint32_t sQl = sb + AQB;
    const uint32_t sKV = sb + 2 * AQB;

    const int ntiles = 2 * qi + 2;

    {
        int row = tid >> 1;
        int c   = (tid & 1) * 4;
        size_t g = ((size_t)(b * SS + q0 + row) * NH + h) * DD;
#pragma unroll
        for (int j = 0; j < 4; j++) {
            cp16(sQh + row * ASTR + (c + j) * 16, qh + g + (c + j) * 8);
            cp16(sQl + row * ASTR + (c + j) * 16, ql + g + (c + j) * 8);
        }
    }
    auto loadKV = [&](int jt, int buf) {
        uint32_t base = sKV + buf * AKVSTG;
        int row = tid >> 2;
        int c   = (tid & 3) * 2;
        size_t g = ((size_t)(b * SS + jt * 64 + row) * NH + h) * DD;
#pragma unroll
        for (int j = 0; j < 2; j++) {
            uint32_t so = row * ASTR + (c + j) * 16;
            size_t go = g + (c + j) * 8;
            cp16(base + 0 * AKB + so, kh + go);
            cp16(base + 1 * AKB + so, kl + go);
            cp16(base + 2 * AKB + so, vh + go);
            cp16(base + 3 * AKB + so, vl + go);
        }
    };
    loadKV(0, 0);
    cp_commit();
    if (ntiles > 1) { loadKV(1, 1); cp_commit(); cp_wait1(); }
    else cp_wait0();
    __syncthreads();

    float mrow[2] = {-1e30f, -1e30f};
    float lrow[2] = {0.0f, 0.0f};
    float oacc[8][4];
#pragma unroll
    for (int nt = 0; nt < 8; nt++)
#pragma unroll
        for (int r = 0; r < 4; r++) oacc[nt][r] = 0.0f;

    const int rowA  = lane & 15;
    const int kofsA = (lane >> 4) * 16;
    const int rowB  = (lane & 7) + ((lane >> 4) & 1) * 8;
    const int kofsB = ((lane >> 3) & 1) * 16;

    for (int jt = 0; jt < ntiles; jt++) {
        const int cur = jt & 1;
        const uint32_t bK  = sKV + cur * AKVSTG;
        const uint32_t bKl = bK + AKB;
        const uint32_t bV  = bK + 2 * AKB;
        const uint32_t bVl = bK + 3 * AKB;

        float sc[8][4];
#pragma unroll
        for (int nt = 0; nt < 8; nt++)
#pragma unroll
            for (int r = 0; r < 4; r++) sc[nt][r] = 0.0f;

#pragma unroll
        for (int ks = 0; ks < 4; ks++) {
            uint32_t ah[4], al[4];
            uint32_t aoff = (wid * 16 + rowA) * ASTR + ks * 32 + kofsA;
            ldm_x4(ah, sQh + aoff);
            ldm_x4(al, sQl + aoff);
#pragma unroll
            for (int nt2 = 0; nt2 < 4; nt2++) {
                uint32_t bh4[4], bl4[4];
                uint32_t boff = (nt2 * 16 + rowB) * ASTR + ks * 32 + kofsB;
                ldm_x4(bh4, bK + boff);
                ldm_x4(bl4, bKl + boff);
                mma16816(sc[2 * nt2],     ah, bh4[0], bh4[1]);
                mma16816(sc[2 * nt2 + 1], ah, bh4[2], bh4[3]);
                mma16816(sc[2 * nt2],     ah, bl4[0], bl4[1]);
                mma16816(sc[2 * nt2 + 1], ah, bl4[2], bl4[3]);
                mma16816(sc[2 * nt2],     al, bh4[0], bh4[1]);
                mma16816(sc[2 * nt2 + 1], al, bh4[2], bh4[3]);
            }
        }

        const int kv0 = jt * 64;
        if (kv0 + 63 > q0 + wid * 16) {
            const int qr = q0 + wid * 16 + (lane >> 2);
#pragma unroll
            for (int nt = 0; nt < 8; nt++) {
#pragma unroll
                for (int r = 0; r < 4; r++) {
                    int qrow = qr + ((r >= 2) ? 8 : 0);
                    int kvc  = kv0 + nt * 8 + (lane & 3) * 2 + (r & 1);
                    if (kvc > qrow) sc[nt][r] = -1e30f;
                }
            }
        }

#pragma unroll
        for (int rh = 0; rh < 2; rh++) {
            float mx = -1e30f;
#pragma unroll
            for (int nt = 0; nt < 8; nt++)
                mx = fmaxf(mx, fmaxf(sc[nt][rh * 2], sc[nt][rh * 2 + 1]));
            mx = fmaxf(mx, __shfl_xor_sync(0xffffffffu, mx, 1));
            mx = fmaxf(mx, __shfl_xor_sync(0xffffffffu, mx, 2));
            float mn = fmaxf(mrow[rh], mx);
            float alpha = __expf(mrow[rh] - mn);
            mrow[rh] = mn;
            float sum = 0.0f;
#pragma unroll
            for (int nt = 0; nt < 8; nt++) {
                float p0 = __expf(sc[nt][rh * 2]     - mn);
                float p1 = __expf(sc[nt][rh * 2 + 1] - mn);
                sc[nt][rh * 2]     = p0;
                sc[nt][rh * 2 + 1] = p1;
                sum += p0 + p1;
            }
            sum += __shfl_xor_sync(0xffffffffu, sum, 1);
            sum += __shfl_xor_sync(0xffffffffu, sum, 2);
            lrow[rh] = lrow[rh] * alpha + sum;
#pragma unroll
            for (int nt = 0; nt < 8; nt++) {
                oacc[nt][rh * 2]     *= alpha;
                oacc[nt][rh * 2 + 1] *= alpha;
            }
        }

        uint32_t ph[4][4], pl[4][4];
#pragma unroll
        for (int ks2 = 0; ks2 < 4; ks2++) {
            const int na = 2 * ks2, nb = 2 * ks2 + 1;
            float pv[4][2] = {{sc[na][0], sc[na][1]}, {sc[na][2], sc[na][3]},
                              {sc[nb][0], sc[nb][1]}, {sc[nb][2], sc[nb][3]}};
#pragma unroll
            for (int a = 0; a < 4; a++) {
                __nv_bfloat16 h0 = __float2bfloat16(pv[a][0]);
                __nv_bfloat16 h1 = __float2bfloat16(pv[a][1]);
                ph[ks2][a] = ((uint32_t)*(uint16_t*)&h1 << 16) | *(uint16_t*)&h0;
                __nv_bfloat16 l0 = __float2bfloat16(pv[a][0] - __bfloat162float(h0));
                __nv_bfloat16 l1 = __float2bfloat16(pv[a][1] - __bfloat162float(h1));
                pl[ks2][a] = ((uint32_t)*(uint16_t*)&l1 << 16) | *(uint16_t*)&l0;
            }
        }

#pragma unroll
        for (int ks2 = 0; ks2 < 4; ks2++) {
#pragma unroll
            for (int nt2 = 0; nt2 < 4; nt2++) {
                uint32_t bvh[4], bvl[4];
                uint32_t voff = (ks2 * 16 + (lane & 15)) * ASTR + (nt2 * 16 + (lane >> 4) * 8) * 2;
                ldm_x4_t(bvh, bV + voff);
                ldm_x4_t(bvl, bVl + voff);
                mma16816(oacc[2 * nt2],     ph[ks2], bvh[0], bvh[1]);
                mma16816(oacc[2 * nt2 + 1], ph[ks2], bvh[2], bvh[3]);
                mma16816(oacc[2 * nt2],     ph[ks2], bvl[0], bvl[1]);
                mma16816(oacc[2 * nt2 + 1], ph[ks2], bvl[2], bvl[3]);
                mma16816(oacc[2 * nt2],     pl[ks2], bvh[0], bvh[1]);
                mma16816(oacc[2 * nt2 + 1], pl[ks2], bvh[2], bvh[3]);
            }
        }

        if (jt + 1 < ntiles) {
            __syncthreads();
            if (jt + 2 < ntiles) { loadKV(jt + 2, cur); cp_commit(); cp_wait1(); }
            else cp_wait0();
            __syncthreads();
        }
    }

    // epilogue: split write to ctx_h/ctx_l
#pragma unroll
    for (int rh = 0; rh < 2; rh++) {
        float inv = 1.0f / lrow[rh];
        int row = q0 + wid * 16 + (lane >> 2) + rh * 8;
        size_t base = ((size_t)(b * SS + row) * NH + h) * DD;
#pragma unroll
        for (int nt = 0; nt < 8; nt++) {
            float x0 = oacc[nt][rh * 2] * inv;
            float x1 = oacc[nt][rh * 2 + 1] * inv;
            size_t idx = base + nt * 8 + (lane & 3) * 2;
            __nv_bfloat16 h0 = __float2bfloat16(x0);
            __nv_bfloat16 h1 = __float2bfloat16(x1);
            __nv_bfloat16 l0 = __float2bfloat16(x0 - __bfloat162float(h0));
            __nv_bfloat16 l1 = __float2bfloat16(x1 - __bfloat162float(h1));
            *(__nv_bfloat162*)&ctxh[idx] = __nv_bfloat162(h0, h1);
            *(__nv_bfloat162*)&ctxl[idx] = __nv_bfloat162(l0, l1);
        }
    }
}

// ---------------- host ----------------
extern "C" void kernel_launch(void* const* d_in, const int* in_sizes, int n_in,
                              void* d_out, int out_size)
{
    const float* hidden = (const float*)d_in[0];
    const float* cosT   = (const float*)d_in[1];
    const float* sinT   = (const float*)d_in[2];
    const float* Wq = (const float*)d_in[4];
    const float* Wk = (const float*)d_in[5];
    const float* Wv = (const float*)d_in[6];
    const float* Wo = (const float*)d_in[7];
    float* out = (float*)d_out;

    float *q, *k;
    cudaGetSymbolAddress((void**)&q, g_q);
    cudaGetSymbolAddress((void**)&k, g_k);

    __nv_bfloat16 *hid_h, *hid_l, *w_h, *w_l, *ctx_h, *ctx_l;
    __nv_bfloat16 *qh, *ql, *kh, *kl, *vh, *vl;
    cudaGetSymbolAddress((void**)&hid_h, g_hid_h);
    cudaGetSymbolAddress((void**)&hid_l, g_hid_l);
    cudaGetSymbolAddress((void**)&w_h,   g_w_h);
    cudaGetSymbolAddress((void**)&w_l,   g_w_l);
    cudaGetSymbolAddress((void**)&ctx_h, g_ctx_h);
    cudaGetSymbolAddress((void**)&ctx_l, g_ctx_l);
    cudaGetSymbolAddress((void**)&qh, g_qh);
    cudaGetSymbolAddress((void**)&ql, g_ql);
    cudaGetSymbolAddress((void**)&kh, g_kh);
    cudaGetSymbolAddress((void**)&kl, g_kl);
    cudaGetSymbolAddress((void**)&vh, g_vh);
    cudaGetSymbolAddress((void**)&vl, g_vl);

    const float* Ws[4] = {Wq, Wk, Wv, Wo};

    int n4h = MM * HID / 4;
    split_kernel<<<(n4h + 255) / 256, 256>>>(hidden, hid_h, hid_l, n4h);
    int n4w = HID * HID / 4;
    for (int w = 0; w < 4; w++)
        split_kernel<<<(n4w + 255) / 256, 256>>>(Ws[w], w_h + (size_t)w * HID * HID,
                                                 w_l + (size_t)w * HID * HID, n4w);

    // fused Q/K/V projections: grid (16, 32, 3)
    gemm_pipe_kernel<<<dim3(16, 32, 3), 256>>>(
        hid_h, hid_l,
        w_h + 0 * (size_t)HID * HID, w_l + 0 * (size_t)HID * HID,
        w_h + 1 * (size_t)HID * HID, w_l + 1 * (size_t)HID * HID,
        w_h + 2 * (size_t)HID * HID, w_l + 2 * (size_t)HID * HID,
        q, k, vh, vl);

    int nrope = BB * SS * NH * (DD / 2);
    rope_split_kernel<<<(nrope + 255) / 256, 256>>>(q, k, cosT, sinT, qh, ql, kh, kl);

    cudaFuncSetAttribute(attn_hmma_kernel, cudaFuncAttributeMaxDynamicSharedMemorySize, ATTN_SMEM);
    dim3 aGrid(SS / 128, NH, BB);
    attn_hmma_kernel<<<aGrid, 256, ATTN_SMEM>>>(qh, ql, kh, kl, vh, vl, ctx_h, ctx_l);

    // output projection: same kernel, z-grid of 1 (z==0 path -> fp32 out)
    gemm_pipe_kernel<<<dim3(16, 32, 1), 256>>>(
        ctx_h, ctx_l,
        w_h + 3 * (size_t)HID * HID, w_l + 3 * (size_t)HID * HID,
        (const __nv_bfloat16*)0, (const __nv_bfloat16*)0,
        (const __nv_bfloat16*)0, (const __nv_bfloat16*)0,
        out, (float*)0, (__nv_bfloat16*)0, (__nv_bfloat16*)0);
}

// round 6
// speedup vs baseline: 3.6546x; 1.3840x over previous
#include <cuda_runtime.h>
#include <cuda_fp16.h>
#include <cstdint>
#include <math.h>

#define BB 2
#define SS 2048
#define HID 1024
#define NH 16
#define DD 64
#define MM (BB*SS)          // 4096

// ---------------- scratch (no allocation allowed) ----------------
__device__ float g_q[BB*SS*HID];
__device__ float g_k[BB*SS*HID];

__device__ __half g_hid_h[MM*HID];
__device__ __half g_hid_l[MM*HID];
__device__ __half g_w[4][HID*HID];      // single fp16 weights
__device__ __half g_ctx_h[MM*HID];
__device__ __half g_ctx_l[MM*HID];

__device__ __half g_qh[MM*HID];
__device__ __half g_ql[MM*HID];
__device__ __half g_kh[MM*HID];
__device__ __half g_v[MM*HID];

// ================= helpers =================
__device__ __forceinline__ uint32_t smem_to_u32(const void* smem_ptr) {
    uint32_t addr;
    asm("{ .reg .u64 tmp; cvta.to.shared.u64 tmp, %1; cvt.u32.u64 %0, tmp; }"
        : "=r"(addr) : "l"(smem_ptr));
    return addr;
}
__device__ __forceinline__ void ldm_x4(uint32_t* r, uint32_t addr) {
    asm volatile("ldmatrix.sync.aligned.m8n8.x4.shared.b16 {%0,%1,%2,%3}, [%4];"
        : "=r"(r[0]), "=r"(r[1]), "=r"(r[2]), "=r"(r[3]) : "r"(addr));
}
__device__ __forceinline__ void ldm_x4_t(uint32_t* r, uint32_t addr) {
    asm volatile("ldmatrix.sync.aligned.m8n8.x4.trans.shared.b16 {%0,%1,%2,%3}, [%4];"
        : "=r"(r[0]), "=r"(r[1]), "=r"(r[2]), "=r"(r[3]) : "r"(addr));
}
// fp16 inputs, fp32 accumulate
__device__ __forceinline__ void mma16816h(float* c, const uint32_t* a, uint32_t b0, uint32_t b1) {
    asm volatile("mma.sync.aligned.m16n8k16.row.col.f32.f16.f16.f32 "
        "{%0,%1,%2,%3}, {%4,%5,%6,%7}, {%8,%9}, {%0,%1,%2,%3};"
        : "+f"(c[0]), "+f"(c[1]), "+f"(c[2]), "+f"(c[3])
        : "r"(a[0]), "r"(a[1]), "r"(a[2]), "r"(a[3]), "r"(b0), "r"(b1));
}
__device__ __forceinline__ void cp16(uint32_t saddr, const void* gaddr) {
    asm volatile("cp.async.cg.shared.global [%0], [%1], 16;" :: "r"(saddr), "l"(gaddr));
}
__device__ __forceinline__ void cp_commit() { asm volatile("cp.async.commit_group;" ::: "memory"); }
__device__ __forceinline__ void cp_wait0() { asm volatile("cp.async.wait_group 0;" ::: "memory"); }
__device__ __forceinline__ void cp_wait1() { asm volatile("cp.async.wait_group 1;" ::: "memory"); }

// ================= fp32 -> fp16 hi/lo split (hidden / ctx) =================
__global__ void split_h_kernel(const float* __restrict__ x,
                               __half* __restrict__ hi,
                               __half* __restrict__ lo, int n4)
{
    int i = blockIdx.x * blockDim.x + threadIdx.x;
    if (i >= n4) return;
    float4 v = ((const float4*)x)[i];
    float vv[4] = {v.x, v.y, v.z, v.w};
    __half h[4], l[4];
#pragma unroll
    for (int j = 0; j < 4; j++) {
        h[j] = __float2half(vv[j]);
        l[j] = __float2half(vv[j] - __half2float(h[j]));
    }
    __half2* hp = (__half2*)hi;
    __half2* lp = (__half2*)lo;
    hp[i * 2 + 0] = __half2(h[0], h[1]);
    hp[i * 2 + 1] = __half2(h[2], h[3]);
    lp[i * 2 + 0] = __half2(l[0], l[1]);
    lp[i * 2 + 1] = __half2(l[2], l[3]);
}

// ================= all 4 weights -> single fp16 =================
__global__ void convert_w_kernel(const float* __restrict__ w0, const float* __restrict__ w1,
                                 const float* __restrict__ w2, const float* __restrict__ w3,
                                 __half* __restrict__ dst)
{
    int i = blockIdx.x * blockDim.x + threadIdx.x;    // float4 units over 4*HID*HID
    const int per = HID * HID / 4;
    if (i >= 4 * per) return;
    int wsel = i / per;
    int j = i - wsel * per;
    const float* src = (wsel == 0) ? w0 : (wsel == 1) ? w1 : (wsel == 2) ? w2 : w3;
    float4 v = ((const float4*)src)[j];
    __half2* dp = (__half2*)(dst + (size_t)wsel * HID * HID);
    dp[j * 2 + 0] = __floats2half2_rn(v.x, v.y);
    dp[j * 2 + 1] = __floats2half2_rn(v.z, v.w);
}

// ================= pipelined fp16 HMMA GEMM, tile 128x64 =================
// C = A @ W^T; A = Ah+Al (fp16 2-digit), W single fp16 -> 2 MMA terms.
#define GROW 80                 // smem row stride bytes (32 fp16 + 16B pad)
#define GA_B (128 * GROW)       // 10240
#define GB_B (64 * GROW)        // 5120
#define GSTG (2 * GA_B + GB_B)  // 25600 per stage
#define GNIT (HID / 32)         // 32 iters

__global__ __launch_bounds__(256, 2) void gemm_fp16_kernel(
    const __half* __restrict__ Ah, const __half* __restrict__ Al,
    const __half* __restrict__ W0, const __half* __restrict__ W1,
    const __half* __restrict__ W2,
    float* __restrict__ c0, float* __restrict__ c1,
    __half* __restrict__ vout)
{
    __shared__ __align__(16) unsigned char smem[2 * GSTG];

    const int tid  = threadIdx.x;
    const int wid  = tid >> 5;
    const int lane = tid & 31;
    const int wm   = wid >> 2;      // 0..1
    const int wn   = wid & 3;       // 0..3
    const int n0   = blockIdx.x * 64;
    const int m0   = blockIdx.y * 128;
    const int z    = blockIdx.z;

    const __half* B = (z == 0) ? W0 : (z == 1) ? W1 : W2;

    const uint32_t sb = smem_to_u32(smem);
    const int rL = tid >> 2;        // 0..63
    const int cL = tid & 3;         // 0..3 (16B chunks)

    auto load_stage = [&](int it, int buf) {
        const int k0 = it * 32;
        uint32_t st = sb + buf * GSTG;
#pragma unroll
        for (int half_ = 0; half_ < 2; half_++) {
            int row = rL + half_ * 64;
            size_t g = (size_t)(m0 + row) * HID + k0 + cL * 8;
            uint32_t so = row * GROW + cL * 16;
            cp16(st + so,        Ah + g);
            cp16(st + GA_B + so, Al + g);
        }
        {
            size_t g = (size_t)(n0 + rL) * HID + k0 + cL * 8;
            uint32_t so = rL * GROW + cL * 16;
            cp16(st + 2 * GA_B + so, B + g);
        }
    };

    float acc[4][2][4];
#pragma unroll
    for (int i = 0; i < 4; i++)
#pragma unroll
        for (int j = 0; j < 2; j++)
#pragma unroll
            for (int r = 0; r < 4; r++) acc[i][j][r] = 0.0f;

    const int rowA  = lane & 15;
    const int kofsA = (lane >> 4) * 16;
    const int rowB  = (lane & 7) + ((lane >> 4) & 1) * 8;
    const int kofsB = ((lane >> 3) & 1) * 16;

    load_stage(0, 0);
    cp_commit();

    for (int it = 0; it < GNIT; it++) {
        const int cur = it & 1;
        cp_wait0();
        __syncthreads();
        if (it + 1 < GNIT) { load_stage(it + 1, cur ^ 1); cp_commit(); }

        const uint32_t sA  = sb + cur * GSTG;
        const uint32_t sAl = sA + GA_B;
        const uint32_t sB  = sA + 2 * GA_B;

#pragma unroll
        for (int kk = 0; kk < 2; kk++) {
            const int kb = kk * 32;
            uint32_t ah[4][4], b4[4];
#pragma unroll
            for (int mt = 0; mt < 4; mt++)
                ldm_x4(ah[mt], sA + (wm * 64 + mt * 16 + rowA) * GROW + kb + kofsA);
            ldm_x4(b4, sB + (wn * 16 + rowB) * GROW + kb + kofsB);
#pragma unroll
            for (int mt = 0; mt < 4; mt++) {
                mma16816h(acc[mt][0], ah[mt], b4[0], b4[1]);
                mma16816h(acc[mt][1], ah[mt], b4[2], b4[3]);
            }
            uint32_t al[4];
#pragma unroll
            for (int mt = 0; mt < 4; mt++) {
                ldm_x4(al, sAl + (wm * 64 + mt * 16 + rowA) * GROW + kb + kofsA);
                mma16816h(acc[mt][0], al, b4[0], b4[1]);
                mma16816h(acc[mt][1], al, b4[2], b4[3]);
            }
        }
        __syncthreads();
    }

    const int rr = lane >> 2;
    const int cc = (lane & 3) * 2;
    if (z == 2) {
#pragma unroll
        for (int mt = 0; mt < 4; mt++) {
#pragma unroll
            for (int nt = 0; nt < 2; nt++) {
                int r = m0 + wm * 64 + mt * 16 + rr;
                int c = n0 + wn * 16 + nt * 8 + cc;
#pragma unroll
                for (int half_ = 0; half_ < 2; half_++) {
                    float x0 = acc[mt][nt][half_ * 2 + 0];
                    float x1 = acc[mt][nt][half_ * 2 + 1];
                    size_t idx = (size_t)(r + half_ * 8) * HID + c;
                    *(__half2*)&vout[idx] = __floats2half2_rn(x0, x1);
                }
            }
        }
    } else {
        float* C = (z == 0) ? c0 : c1;
#pragma unroll
        for (int mt = 0; mt < 4; mt++) {
#pragma unroll
            for (int nt = 0; nt < 2; nt++) {
                int r = m0 + wm * 64 + mt * 16 + rr;
                int c = n0 + wn * 16 + nt * 8 + cc;
                *(float2*)&C[(size_t)r * HID + c] =
                    make_float2(acc[mt][nt][0], acc[mt][nt][1]);
                *(float2*)&C[(size_t)(r + 8) * HID + c] =
                    make_float2(acc[mt][nt][2], acc[mt][nt][3]);
            }
        }
    }
}

// ---------------- RoPE + quantize: q -> (qh,ql) scaled 1/8; k -> fp16 single ----------------
__global__ void rope_split_kernel(const float* __restrict__ q, const float* __restrict__ k,
                                  const float* __restrict__ cosT, const float* __restrict__ sinT,
                                  __half* __restrict__ qh, __half* __restrict__ ql,
                                  __half* __restrict__ kh)
{
    int idx = blockIdx.x * blockDim.x + threadIdx.x;
    if (idx >= BB * SS * NH * (DD / 2)) return;
    int p = idx & 31;
    int s = (idx >> 9) & (SS - 1);
    float c  = cosT[s * 32 + p];
    float sn = sinT[s * 32 + p];
    int base = idx * 2;

    float a = q[base], b = q[base + 1];
    float r0 = (a * c - b * sn) * 0.125f;
    float r1 = (a * sn + b * c) * 0.125f;
    __half h0 = __float2half(r0), h1 = __float2half(r1);
    qh[base] = h0; qh[base + 1] = h1;
    ql[base]     = __float2half(r0 - __half2float(h0));
    ql[base + 1] = __float2half(r1 - __half2float(h1));

    a = k[base]; b = k[base + 1];
    *(__half2*)&kh[base] = __floats2half2_rn(a * c - b * sn, a * sn + b * c);
}

// ---------------- fp16 HMMA flash attention (causal) ----------------
// scores: (qh+ql) x k  (2 terms);  PV: P_fp16 x V_fp16 (1 term)
#define ASTR 144
#define AQB  (128 * ASTR)       // 18432
#define AKB  (64 * ASTR)        // 9216
#define AKVSTG (2 * AKB)        // K + V = 18432
#define ATTN_SMEM (2 * AQB + 2 * AKVSTG)   // 73728

__global__ __launch_bounds__(256, 2) void attn_hmma_kernel(
    const __half* __restrict__ qh, const __half* __restrict__ ql,
    const __half* __restrict__ kh, const __half* __restrict__ vv,
    __half* __restrict__ ctxh, __half* __restrict__ ctxl)
{
    extern __shared__ unsigned char sm[];
    const int qi  = blockIdx.x;
    const int h   = blockIdx.y;
    const int b   = blockIdx.z;
    const int tid = threadIdx.x;
    const int wid = tid >> 5;
    const int lane = tid & 31;
    const int q0  = qi * 128;

    const uint32_t sb  = smem_to_u32(sm);
    const uint32_t sQh = sb;
    const uint32_t sQl = sb + AQB;
    const uint32_t sKV = sb + 2 * AQB;

    const int ntiles = 2 * qi + 2;

    {
        int row = tid >> 1;
        int c   = (tid & 1) * 4;
        size_t g = ((size_t)(b * SS + q0 + row) * NH + h) * DD;
#pragma unroll
        for (int j = 0; j < 4; j++) {
            cp16(sQh + row * ASTR + (c + j) * 16, qh + g + (c + j) * 8);
            cp16(sQl + row * ASTR + (c + j) * 16, ql + g + (c + j) * 8);
        }
    }
    auto loadKV = [&](int jt, int buf) {
        uint32_t base = sKV + buf * AKVSTG;
        int row = tid >> 2;
        int c   = (tid & 3) * 2;
        size_t g = ((size_t)(b * SS + jt * 64 + row) * NH + h) * DD;
#pragma unroll
        for (int j = 0; j < 2; j++) {
            uint32_t so = row * ASTR + (c + j) * 16;
            size_t go = g + (c + j) * 8;
            cp16(base + so,       kh + go);
            cp16(base + AKB + so, vv + go);
        }
    };
    loadKV(0, 0);
    cp_commit();
    if (ntiles > 1) { loadKV(1, 1); cp_commit(); cp_wait1(); }
    else cp_wait0();
    __syncthreads();

    float mrow[2] = {-1e30f, -1e30f};
    float lrow[2] = {0.0f, 0.0f};
    float oacc[8][4];
#pragma unroll
    for (int nt = 0; nt < 8; nt++)
#pragma unroll
        for (int r = 0; r < 4; r++) oacc[nt][r] = 0.0f;

    const int rowA  = lane & 15;
    const int kofsA = (lane >> 4) * 16;
    const int rowB  = (lane & 7) + ((lane >> 4) & 1) * 8;
    const int kofsB = ((lane >> 3) & 1) * 16;

    for (int jt = 0; jt < ntiles; jt++) {
        const int cur = jt & 1;
        const uint32_t bK = sKV + cur * AKVSTG;
        const uint32_t bV = bK + AKB;

        float sc[8][4];
#pragma unroll
        for (int nt = 0; nt < 8; nt++)
#pragma unroll
            for (int r = 0; r < 4; r++) sc[nt][r] = 0.0f;

#pragma unroll
        for (int ks = 0; ks < 4; ks++) {
            uint32_t ah[4], al[4];
            uint32_t aoff = (wid * 16 + rowA) * ASTR + ks * 32 + kofsA;
            ldm_x4(ah, sQh + aoff);
            ldm_x4(al, sQl + aoff);
#pragma unroll
            for (int nt2 = 0; nt2 < 4; nt2++) {
                uint32_t b4[4];
                uint32_t boff = (nt2 * 16 + rowB) * ASTR + ks * 32 + kofsB;
                ldm_x4(b4, bK + boff);
                mma16816h(sc[2 * nt2],     ah, b4[0], b4[1]);
                mma16816h(sc[2 * nt2 + 1], ah, b4[2], b4[3]);
                mma16816h(sc[2 * nt2],     al, b4[0], b4[1]);
                mma16816h(sc[2 * nt2 + 1], al, b4[2], b4[3]);
            }
        }

        const int kv0 = jt * 64;
        if (kv0 + 63 > q0 + wid * 16) {
            const int qr = q0 + wid * 16 + (lane >> 2);
#pragma unroll
            for (int nt = 0; nt < 8; nt++) {
#pragma unroll
                for (int r = 0; r < 4; r++) {
                    int qrow = qr + ((r >= 2) ? 8 : 0);
                    int kvc  = kv0 + nt * 8 + (lane & 3) * 2 + (r & 1);
                    if (kvc > qrow) sc[nt][r] = -1e30f;
                }
            }
        }

#pragma unroll
        for (int rh = 0; rh < 2; rh++) {
            float mx = -1e30f;
#pragma unroll
            for (int nt = 0; nt < 8; nt++)
                mx = fmaxf(mx, fmaxf(sc[nt][rh * 2], sc[nt][rh * 2 + 1]));
            mx = fmaxf(mx, __shfl_xor_sync(0xffffffffu, mx, 1));
            mx = fmaxf(mx, __shfl_xor_sync(0xffffffffu, mx, 2));
            float mn = fmaxf(mrow[rh], mx);
            float alpha = __expf(mrow[rh] - mn);
            mrow[rh] = mn;
            float sum = 0.0f;
#pragma unroll
            for (int nt = 0; nt < 8; nt++) {
                float p0 = __expf(sc[nt][rh * 2]     - mn);
                float p1 = __expf(sc[nt][rh * 2 + 1] - mn);
                sc[nt][rh * 2]     = p0;
                sc[nt][rh * 2 + 1] = p1;
                sum += p0 + p1;
            }
            sum += __shfl_xor_sync(0xffffffffu, sum, 1);
            sum += __shfl_xor_sync(0xffffffffu, sum, 2);
            lrow[rh] = lrow[rh] * alpha + sum;
#pragma unroll
            for (int nt = 0; nt < 8; nt++) {
                oacc[nt][rh * 2]     *= alpha;
                oacc[nt][rh * 2 + 1] *= alpha;
            }
        }

        // P fragments as single fp16
        uint32_t ph[4][4];
#pragma unroll
        for (int ks2 = 0; ks2 < 4; ks2++) {
            const int na = 2 * ks2, nb = 2 * ks2 + 1;
            ph[ks2][0] = *(uint32_t*)&(__half2&)*(__half2[]){__floats2half2_rn(sc[na][0], sc[na][1])};
            ph[ks2][0] = *(uint32_t*)&(const __half2&)__floats2half2_rn(sc[na][0], sc[na][1]);
            __half2 t0 = __floats2half2_rn(sc[na][0], sc[na][1]);
            __half2 t1 = __floats2half2_rn(sc[na][2], sc[na][3]);
            __half2 t2 = __floats2half2_rn(sc[nb][0], sc[nb][1]);
            __half2 t3 = __floats2half2_rn(sc[nb][2], sc[nb][3]);
            ph[ks2][0] = *(uint32_t*)&t0;
            ph[ks2][1] = *(uint32_t*)&t1;
            ph[ks2][2] = *(uint32_t*)&t2;
            ph[ks2][3] = *(uint32_t*)&t3;
        }

        // O += P V (single term)
#pragma unroll
        for (int ks2 = 0; ks2 < 4; ks2++) {
#pragma unroll
            for (int nt2 = 0; nt2 < 4; nt2++) {
                uint32_t bv[4];
                uint32_t voff = (ks2 * 16 + (lane & 15)) * ASTR + (nt2 * 16 + (lane >> 4) * 8) * 2;
                ldm_x4_t(bv, bV + voff);
                mma16816h(oacc[2 * nt2],     ph[ks2], bv[0], bv[1]);
                mma16816h(oacc[2 * nt2 + 1], ph[ks2], bv[2], bv[3]);
            }
        }

        if (jt + 1 < ntiles) {
            __syncthreads();
            if (jt + 2 < ntiles) { loadKV(jt + 2, cur); cp_commit(); cp_wait1(); }
            else cp_wait0();
            __syncthreads();
        }
    }

    // epilogue: 2-digit fp16 split write for Wo GEMM
#pragma unroll
    for (int rh = 0; rh < 2; rh++) {
        float inv = 1.0f / lrow[rh];
        int row = q0 + wid * 16 + (lane >> 2) + rh * 8;
        size_t base = ((size_t)(b * SS + row) * NH + h) * DD;
#pragma unroll
        for (int nt = 0; nt < 8; nt++) {
            float x0 = oacc[nt][rh * 2] * inv;
            float x1 = oacc[nt][rh * 2 + 1] * inv;
            size_t idx = base + nt * 8 + (lane & 3) * 2;
            __half h0 = __float2half(x0);
            __half h1 = __float2half(x1);
            __half l0 = __float2half(x0 - __half2float(h0));
            __half l1 = __float2half(x1 - __half2float(h1));
            *(__half2*)&ctxh[idx] = __half2(h0, h1);
            *(__half2*)&ctxl[idx] = __half2(l0, l1);
        }
    }
}

// ---------------- host ----------------
extern "C" void kernel_launch(void* const* d_in, const int* in_sizes, int n_in,
                              void* d_out, int out_size)
{
    const float* hidden = (const float*)d_in[0];
    const float* cosT   = (const float*)d_in[1];
    const float* sinT   = (const float*)d_in[2];
    const float* Wq = (const float*)d_in[4];
    const float* Wk = (const float*)d_in[5];
    const float* Wv = (const float*)d_in[6];
    const float* Wo = (const float*)d_in[7];
    float* out = (float*)d_out;

    float *q, *k;
    cudaGetSymbolAddress((void**)&q, g_q);
    cudaGetSymbolAddress((void**)&k, g_k);

    __half *hid_h, *hid_l, *w, *ctx_h, *ctx_l, *qh, *ql, *kh, *v;
    cudaGetSymbolAddress((void**)&hid_h, g_hid_h);
    cudaGetSymbolAddress((void**)&hid_l, g_hid_l);
    cudaGetSymbolAddress((void**)&w,     g_w);
    cudaGetSymbolAddress((void**)&ctx_h, g_ctx_h);
    cudaGetSymbolAddress((void**)&ctx_l, g_ctx_l);
    cudaGetSymbolAddress((void**)&qh, g_qh);
    cudaGetSymbolAddress((void**)&ql, g_ql);
    cudaGetSymbolAddress((void**)&kh, g_kh);
    cudaGetSymbolAddress((void**)&v,  g_v);

    int n4h = MM * HID / 4;
    split_h_kernel<<<(n4h + 255) / 256, 256>>>(hidden, hid_h, hid_l, n4h);

    int n4w = 4 * HID * HID / 4;
    convert_w_kernel<<<(n4w + 255) / 256, 256>>>(Wq, Wk, Wv, Wo, w);

    // fused Q/K/V projections
    gemm_fp16_kernel<<<dim3(16, 32, 3), 256>>>(
        hid_h, hid_l,
        w + 0 * (size_t)HID * HID, w + 1 * (size_t)HID * HID, w + 2 * (size_t)HID * HID,
        q, k, v);

    int nrope = BB * SS * NH * (DD / 2);
    rope_split_kernel<<<(nrope + 255) / 256, 256>>>(q, k, cosT, sinT, qh, ql, kh);

    cudaFuncSetAttribute(attn_hmma_kernel, cudaFuncAttributeMaxDynamicSharedMemorySize, ATTN_SMEM);
    dim3 aGrid(SS / 128, NH, BB);
    attn_hmma_kernel<<<aGrid, 256, ATTN_SMEM>>>(qh, ql, kh, v, ctx_h, ctx_l);

    // output projection (z==0 -> fp32 out)
    gemm_fp16_kernel<<<dim3(16, 32, 1), 256>>>(
        ctx_h, ctx_l,
        w + 3 * (size_t)HID * HID, (const __half*)0, (const __half*)0,
        out, (float*)0, (__half*)0);
}

// round 7
// speedup vs baseline: 3.8385x; 1.0503x over previous
#include <cuda_runtime.h>
#include <cuda_fp16.h>
#include <cstdint>
#include <math.h>

#define BB 2
#define SS 2048
#define HID 1024
#define NH 16
#define DD 64
#define MM (BB*SS)          // 4096

// ---------------- scratch (no allocation allowed) ----------------
__device__ __half g_hid_h[MM*HID];
__device__ __half g_hid_l[MM*HID];
__device__ __half g_w[4][HID*HID];      // single fp16 weights
__device__ __half g_ctx_h[MM*HID];
__device__ __half g_ctx_l[MM*HID];

__device__ __half g_qh[MM*HID];
__device__ __half g_kh[MM*HID];
__device__ __half g_v[MM*HID];

// ================= helpers =================
__device__ __forceinline__ uint32_t smem_to_u32(const void* smem_ptr) {
    uint32_t addr;
    asm("{ .reg .u64 tmp; cvta.to.shared.u64 tmp, %1; cvt.u32.u64 %0, tmp; }"
        : "=r"(addr) : "l"(smem_ptr));
    return addr;
}
__device__ __forceinline__ void ldm_x4(uint32_t* r, uint32_t addr) {
    asm volatile("ldmatrix.sync.aligned.m8n8.x4.shared.b16 {%0,%1,%2,%3}, [%4];"
        : "=r"(r[0]), "=r"(r[1]), "=r"(r[2]), "=r"(r[3]) : "r"(addr));
}
__device__ __forceinline__ void ldm_x4_t(uint32_t* r, uint32_t addr) {
    asm volatile("ldmatrix.sync.aligned.m8n8.x4.trans.shared.b16 {%0,%1,%2,%3}, [%4];"
        : "=r"(r[0]), "=r"(r[1]), "=r"(r[2]), "=r"(r[3]) : "r"(addr));
}
// fp16 inputs, fp32 accumulate
__device__ __forceinline__ void mma16816h(float* c, const uint32_t* a, uint32_t b0, uint32_t b1) {
    asm volatile("mma.sync.aligned.m16n8k16.row.col.f32.f16.f16.f32 "
        "{%0,%1,%2,%3}, {%4,%5,%6,%7}, {%8,%9}, {%0,%1,%2,%3};"
        : "+f"(c[0]), "+f"(c[1]), "+f"(c[2]), "+f"(c[3])
        : "r"(a[0]), "r"(a[1]), "r"(a[2]), "r"(a[3]), "r"(b0), "r"(b1));
}
// fp16 inputs, fp16 accumulate (for small correction terms)
__device__ __forceinline__ void mma16816hacc(uint32_t* c, const uint32_t* a, uint32_t b0, uint32_t b1) {
    asm volatile("mma.sync.aligned.m16n8k16.row.col.f16.f16.f16.f16 "
        "{%0,%1}, {%2,%3,%4,%5}, {%6,%7}, {%0,%1};"
        : "+r"(c[0]), "+r"(c[1])
        : "r"(a[0]), "r"(a[1]), "r"(a[2]), "r"(a[3]), "r"(b0), "r"(b1));
}
__device__ __forceinline__ void cp16(uint32_t saddr, const void* gaddr) {
    asm volatile("cp.async.cg.shared.global [%0], [%1], 16;" :: "r"(saddr), "l"(gaddr));
}
__device__ __forceinline__ void cp_commit() { asm volatile("cp.async.commit_group;" ::: "memory"); }
__device__ __forceinline__ void cp_wait0() { asm volatile("cp.async.wait_group 0;" ::: "memory"); }
__device__ __forceinline__ void cp_wait1() { asm volatile("cp.async.wait_group 1;" ::: "memory"); }

// ================= fp32 -> fp16 hi/lo split (hidden) =================
__global__ void split_h_kernel(const float* __restrict__ x,
                               __half* __restrict__ hi,
                               __half* __restrict__ lo, int n4)
{
    int i = blockIdx.x * blockDim.x + threadIdx.x;
    if (i >= n4) return;
    float4 v = ((const float4*)x)[i];
    float vv[4] = {v.x, v.y, v.z, v.w};
    __half h[4], l[4];
#pragma unroll
    for (int j = 0; j < 4; j++) {
        h[j] = __float2half(vv[j]);
        l[j] = __float2half(vv[j] - __half2float(h[j]));
    }
    __half2* hp = (__half2*)hi;
    __half2* lp = (__half2*)lo;
    hp[i * 2 + 0] = __half2(h[0], h[1]);
    hp[i * 2 + 1] = __half2(h[2], h[3]);
    lp[i * 2 + 0] = __half2(l[0], l[1]);
    lp[i * 2 + 1] = __half2(l[2], l[3]);
}

// ================= all 4 weights -> single fp16 =================
__global__ void convert_w_kernel(const float* __restrict__ w0, const float* __restrict__ w1,
                                 const float* __restrict__ w2, const float* __restrict__ w3,
                                 __half* __restrict__ dst)
{
    int i = blockIdx.x * blockDim.x + threadIdx.x;
    const int per = HID * HID / 4;
    if (i >= 4 * per) return;
    int wsel = i / per;
    int j = i - wsel * per;
    const float* src = (wsel == 0) ? w0 : (wsel == 1) ? w1 : (wsel == 2) ? w2 : w3;
    float4 v = ((const float4*)src)[j];
    __half2* dp = (__half2*)(dst + (size_t)wsel * HID * HID);
    dp[j * 2 + 0] = __floats2half2_rn(v.x, v.y);
    dp[j * 2 + 1] = __floats2half2_rn(v.z, v.w);
}

// ================= pipelined fp16 HMMA GEMM, tile 128x64 =================
// hi term -> fp32 acc; lo term (Ah?no: Al x W) -> fp16 acc, combined at epilogue.
// mode 0 (QKV): z0 -> rope+scale -> qh, z1 -> rope -> kh, z2 -> v fp16
// mode 1 (Wo):  z0 -> fp32 out
#define GROW 80
#define GA_B (128 * GROW)       // 10240
#define GB_B (64 * GROW)        // 5120
#define GSTG (2 * GA_B + GB_B)  // 25600
#define GNIT (HID / 32)         // 32

__global__ __launch_bounds__(256, 2) void gemm_fp16_kernel(
    const __half* __restrict__ Ah, const __half* __restrict__ Al,
    const __half* __restrict__ W0, const __half* __restrict__ W1,
    const __half* __restrict__ W2,
    const float* __restrict__ cosT, const float* __restrict__ sinT,
    float* __restrict__ c0,
    __half* __restrict__ qout, __half* __restrict__ kout, __half* __restrict__ vout,
    int mode)
{
    __shared__ __align__(16) unsigned char smem[2 * GSTG];

    const int tid  = threadIdx.x;
    const int wid  = tid >> 5;
    const int lane = tid & 31;
    const int wm   = wid >> 2;      // 0..1
    const int wn   = wid & 3;       // 0..3
    const int n0   = blockIdx.x * 64;
    const int m0   = blockIdx.y * 128;
    const int z    = blockIdx.z;

    const __half* B = (z == 0) ? W0 : (z == 1) ? W1 : W2;

    const uint32_t sb = smem_to_u32(smem);
    const int rL = tid >> 2;
    const int cL = tid & 3;

    auto load_stage = [&](int it, int buf) {
        const int k0 = it * 32;
        uint32_t st = sb + buf * GSTG;
#pragma unroll
        for (int half_ = 0; half_ < 2; half_++) {
            int row = rL + half_ * 64;
            size_t g = (size_t)(m0 + row) * HID + k0 + cL * 8;
            uint32_t so = row * GROW + cL * 16;
            cp16(st + so,        Ah + g);
            cp16(st + GA_B + so, Al + g);
        }
        {
            size_t g = (size_t)(n0 + rL) * HID + k0 + cL * 8;
            uint32_t so = rL * GROW + cL * 16;
            cp16(st + 2 * GA_B + so, B + g);
        }
    };

    float acc[4][2][4];
    uint32_t accl[4][2][2];
#pragma unroll
    for (int i = 0; i < 4; i++)
#pragma unroll
        for (int j = 0; j < 2; j++) {
#pragma unroll
            for (int r = 0; r < 4; r++) acc[i][j][r] = 0.0f;
            accl[i][j][0] = 0u; accl[i][j][1] = 0u;
        }

    const int rowA  = lane & 15;
    const int kofsA = (lane >> 4) * 16;
    const int rowB  = (lane & 7) + ((lane >> 4) & 1) * 8;
    const int kofsB = ((lane >> 3) & 1) * 16;

    load_stage(0, 0);
    cp_commit();

    for (int it = 0; it < GNIT; it++) {
        const int cur = it & 1;
        cp_wait0();
        __syncthreads();
        if (it + 1 < GNIT) { load_stage(it + 1, cur ^ 1); cp_commit(); }

        const uint32_t sA  = sb + cur * GSTG;
        const uint32_t sAl = sA + GA_B;
        const uint32_t sB  = sA + 2 * GA_B;

#pragma unroll
        for (int kk = 0; kk < 2; kk++) {
            const int kb = kk * 32;
            uint32_t ah[4][4], b4[4];
#pragma unroll
            for (int mt = 0; mt < 4; mt++)
                ldm_x4(ah[mt], sA + (wm * 64 + mt * 16 + rowA) * GROW + kb + kofsA);
            ldm_x4(b4, sB + (wn * 16 + rowB) * GROW + kb + kofsB);
#pragma unroll
            for (int mt = 0; mt < 4; mt++) {
                mma16816h(acc[mt][0], ah[mt], b4[0], b4[1]);
                mma16816h(acc[mt][1], ah[mt], b4[2], b4[3]);
            }
            uint32_t al[4];
#pragma unroll
            for (int mt = 0; mt < 4; mt++) {
                ldm_x4(al, sAl + (wm * 64 + mt * 16 + rowA) * GROW + kb + kofsA);
                mma16816hacc(accl[mt][0], al, b4[0], b4[1]);
                mma16816hacc(accl[mt][1], al, b4[2], b4[3]);
            }
        }
        __syncthreads();
    }

    // combine lo-term (fp16 acc) into fp32 acc
#pragma unroll
    for (int mt = 0; mt < 4; mt++)
#pragma unroll
        for (int nt = 0; nt < 2; nt++) {
            __half2 lo0 = *(__half2*)&accl[mt][nt][0];
            __half2 lo1 = *(__half2*)&accl[mt][nt][1];
            acc[mt][nt][0] += __low2float(lo0);
            acc[mt][nt][1] += __high2float(lo0);
            acc[mt][nt][2] += __low2float(lo1);
            acc[mt][nt][3] += __high2float(lo1);
        }

    const int rr = lane >> 2;
    const int cc = (lane & 3) * 2;

    if (mode == 1) {
        // fp32 output (Wo projection)
#pragma unroll
        for (int mt = 0; mt < 4; mt++)
#pragma unroll
            for (int nt = 0; nt < 2; nt++) {
                int r = m0 + wm * 64 + mt * 16 + rr;
                int c = n0 + wn * 16 + nt * 8 + cc;
                *(float2*)&c0[(size_t)r * HID + c] =
                    make_float2(acc[mt][nt][0], acc[mt][nt][1]);
                *(float2*)&c0[(size_t)(r + 8) * HID + c] =
                    make_float2(acc[mt][nt][2], acc[mt][nt][3]);
            }
        return;
    }

    if (z == 2) {
        // V -> fp16
#pragma unroll
        for (int mt = 0; mt < 4; mt++)
#pragma unroll
            for (int nt = 0; nt < 2; nt++) {
                int r = m0 + wm * 64 + mt * 16 + rr;
                int c = n0 + wn * 16 + nt * 8 + cc;
#pragma unroll
                for (int half_ = 0; half_ < 2; half_++) {
                    size_t idx = (size_t)(r + half_ * 8) * HID + c;
                    *(__half2*)&vout[idx] =
                        __floats2half2_rn(acc[mt][nt][half_ * 2], acc[mt][nt][half_ * 2 + 1]);
                }
            }
    } else {
        // Q (z==0, scaled 1/8) or K (z==1): apply RoPE in-register, write fp16
        __half* dst = (z == 0) ? qout : kout;
        const float scale = (z == 0) ? 0.125f : 1.0f;
#pragma unroll
        for (int mt = 0; mt < 4; mt++)
#pragma unroll
            for (int nt = 0; nt < 2; nt++) {
                int c = n0 + wn * 16 + nt * 8 + cc;       // even
                int p = (c & 63) >> 1;
#pragma unroll
                for (int half_ = 0; half_ < 2; half_++) {
                    int r = m0 + wm * 64 + mt * 16 + rr + half_ * 8;
                    int s = r & (SS - 1);
                    float co = cosT[s * 32 + p];
                    float si = sinT[s * 32 + p];
                    float a = acc[mt][nt][half_ * 2];
                    float b = acc[mt][nt][half_ * 2 + 1];
                    float o0 = (a * co - b * si) * scale;
                    float o1 = (a * si + b * co) * scale;
                    *(__half2*)&dst[(size_t)r * HID + c] = __floats2half2_rn(o0, o1);
                }
            }
    }
}

// ---------------- fp16 HMMA flash attention (causal) ----------------
// scores: q_fp16 x k_fp16 (1 term);  PV: P_fp16 x V_fp16 (1 term)
#define ASTR 144
#define AQB  (128 * ASTR)       // 18432
#define AKB  (64 * ASTR)        // 9216
#define AKVSTG (2 * AKB)        // 18432
#define ATTN_SMEM (AQB + 2 * AKVSTG)   // 55296

__global__ __launch_bounds__(256, 2) void attn_hmma_kernel(
    const __half* __restrict__ qh, const __half* __restrict__ kh,
    const __half* __restrict__ vv,
    __half* __restrict__ ctxh, __half* __restrict__ ctxl)
{
    extern __shared__ unsigned char sm[];
    const int qi  = blockIdx.x;
    const int h   = blockIdx.y;
    const int b   = blockIdx.z;
    const int tid = threadIdx.x;
    const int wid = tid >> 5;
    const int lane = tid & 31;
    const int q0  = qi * 128;

    const uint32_t sb  = smem_to_u32(sm);
    const uint32_t sQh = sb;
    const uint32_t sKV = sb + AQB;

    const int ntiles = 2 * qi + 2;

    {
        int row = tid >> 1;
        int c   = (tid & 1) * 4;
        size_t g = ((size_t)(b * SS + q0 + row) * NH + h) * DD;
#pragma unroll
        for (int j = 0; j < 4; j++)
            cp16(sQh + row * ASTR + (c + j) * 16, qh + g + (c + j) * 8);
    }
    auto loadKV = [&](int jt, int buf) {
        uint32_t base = sKV + buf * AKVSTG;
        int row = tid >> 2;
        int c   = (tid & 3) * 2;
        size_t g = ((size_t)(b * SS + jt * 64 + row) * NH + h) * DD;
#pragma unroll
        for (int j = 0; j < 2; j++) {
            uint32_t so = row * ASTR + (c + j) * 16;
            size_t go = g + (c + j) * 8;
            cp16(base + so,       kh + go);
            cp16(base + AKB + so, vv + go);
        }
    };
    loadKV(0, 0);
    cp_commit();
    if (ntiles > 1) { loadKV(1, 1); cp_commit(); cp_wait1(); }
    else cp_wait0();
    __syncthreads();

    float mrow[2] = {-1e30f, -1e30f};
    float lrow[2] = {0.0f, 0.0f};
    float oacc[8][4];
#pragma unroll
    for (int nt = 0; nt < 8; nt++)
#pragma unroll
        for (int r = 0; r < 4; r++) oacc[nt][r] = 0.0f;

    const int rowA  = lane & 15;
    const int kofsA = (lane >> 4) * 16;
    const int rowB  = (lane & 7) + ((lane >> 4) & 1) * 8;
    const int kofsB = ((lane >> 3) & 1) * 16;

    for (int jt = 0; jt < ntiles; jt++) {
        const int cur = jt & 1;
        const uint32_t bK = sKV + cur * AKVSTG;
        const uint32_t bV = bK + AKB;

        float sc[8][4];
#pragma unroll
        for (int nt = 0; nt < 8; nt++)
#pragma unroll
            for (int r = 0; r < 4; r++) sc[nt][r] = 0.0f;

#pragma unroll
        for (int ks = 0; ks < 4; ks++) {
            uint32_t ah[4];
            ldm_x4(ah, sQh + (wid * 16 + rowA) * ASTR + ks * 32 + kofsA);
#pragma unroll
            for (int nt2 = 0; nt2 < 4; nt2++) {
                uint32_t b4[4];
                ldm_x4(b4, bK + (nt2 * 16 + rowB) * ASTR + ks * 32 + kofsB);
                mma16816h(sc[2 * nt2],     ah, b4[0], b4[1]);
                mma16816h(sc[2 * nt2 + 1], ah, b4[2], b4[3]);
            }
        }

        const int kv0 = jt * 64;
        if (kv0 + 63 > q0 + wid * 16) {
            const int qr = q0 + wid * 16 + (lane >> 2);
#pragma unroll
            for (int nt = 0; nt < 8; nt++) {
#pragma unroll
                for (int r = 0; r < 4; r++) {
                    int qrow = qr + ((r >= 2) ? 8 : 0);
                    int kvc  = kv0 + nt * 8 + (lane & 3) * 2 + (r & 1);
                    if (kvc > qrow) sc[nt][r] = -1e30f;
                }
            }
        }

#pragma unroll
        for (int rh = 0; rh < 2; rh++) {
            float mx = -1e30f;
#pragma unroll
            for (int nt = 0; nt < 8; nt++)
                mx = fmaxf(mx, fmaxf(sc[nt][rh * 2], sc[nt][rh * 2 + 1]));
            mx = fmaxf(mx, __shfl_xor_sync(0xffffffffu, mx, 1));
            mx = fmaxf(mx, __shfl_xor_sync(0xffffffffu, mx, 2));
            float mn = fmaxf(mrow[rh], mx);
            float alpha = __expf(mrow[rh] - mn);
            mrow[rh] = mn;
            float sum = 0.0f;
#pragma unroll
            for (int nt = 0; nt < 8; nt++) {
                float p0 = __expf(sc[nt][rh * 2]     - mn);
                float p1 = __expf(sc[nt][rh * 2 + 1] - mn);
                sc[nt][rh * 2]     = p0;
                sc[nt][rh * 2 + 1] = p1;
                sum += p0 + p1;
            }
            sum += __shfl_xor_sync(0xffffffffu, sum, 1);
            sum += __shfl_xor_sync(0xffffffffu, sum, 2);
            lrow[rh] = lrow[rh] * alpha + sum;
#pragma unroll
            for (int nt = 0; nt < 8; nt++) {
                oacc[nt][rh * 2]     *= alpha;
                oacc[nt][rh * 2 + 1] *= alpha;
            }
        }

        uint32_t ph[4][4];
#pragma unroll
        for (int ks2 = 0; ks2 < 4; ks2++) {
            const int na = 2 * ks2, nb = 2 * ks2 + 1;
            __half2 t0 = __floats2half2_rn(sc[na][0], sc[na][1]);
            __half2 t1 = __floats2half2_rn(sc[na][2], sc[na][3]);
            __half2 t2 = __floats2half2_rn(sc[nb][0], sc[nb][1]);
            __half2 t3 = __floats2half2_rn(sc[nb][2], sc[nb][3]);
            ph[ks2][0] = *(uint32_t*)&t0;
            ph[ks2][1] = *(uint32_t*)&t1;
            ph[ks2][2] = *(uint32_t*)&t2;
            ph[ks2][3] = *(uint32_t*)&t3;
        }

#pragma unroll
        for (int ks2 = 0; ks2 < 4; ks2++) {
#pragma unroll
            for (int nt2 = 0; nt2 < 4; nt2++) {
                uint32_t bv[4];
                uint32_t voff = (ks2 * 16 + (lane & 15)) * ASTR + (nt2 * 16 + (lane >> 4) * 8) * 2;
                ldm_x4_t(bv, bV + voff);
                mma16816h(oacc[2 * nt2],     ph[ks2], bv[0], bv[1]);
                mma16816h(oacc[2 * nt2 + 1], ph[ks2], bv[2], bv[3]);
            }
        }

        if (jt + 1 < ntiles) {
            __syncthreads();
            if (jt + 2 < ntiles) { loadKV(jt + 2, cur); cp_commit(); cp_wait1(); }
            else cp_wait0();
            __syncthreads();
        }
    }

    // epilogue: 2-digit fp16 split write for Wo GEMM
#pragma unroll
    for (int rh = 0; rh < 2; rh++) {
        float inv = 1.0f / lrow[rh];
        int row = q0 + wid * 16 + (lane >> 2) + rh * 8;
        size_t base = ((size_t)(b * SS + row) * NH + h) * DD;
#pragma unroll
        for (int nt = 0; nt < 8; nt++) {
            float x0 = oacc[nt][rh * 2] * inv;
            float x1 = oacc[nt][rh * 2 + 1] * inv;
            size_t idx = base + nt * 8 + (lane & 3) * 2;
            __half h0 = __float2half(x0);
            __half h1 = __float2half(x1);
            __half l0 = __float2half(x0 - __half2float(h0));
            __half l1 = __float2half(x1 - __half2float(h1));
            *(__half2*)&ctxh[idx] = __half2(h0, h1);
            *(__half2*)&ctxl[idx] = __half2(l0, l1);
        }
    }
}

// ---------------- host ----------------
extern "C" void kernel_launch(void* const* d_in, const int* in_sizes, int n_in,
                              void* d_out, int out_size)
{
    const float* hidden = (const float*)d_in[0];
    const float* cosT   = (const float*)d_in[1];
    const float* sinT   = (const float*)d_in[2];
    const float* Wq = (const float*)d_in[4];
    const float* Wk = (const float*)d_in[5];
    const float* Wv = (const float*)d_in[6];
    const float* Wo = (const float*)d_in[7];
    float* out = (float*)d_out;

    __half *hid_h, *hid_l, *w, *ctx_h, *ctx_l, *qh, *kh, *v;
    cudaGetSymbolAddress((void**)&hid_h, g_hid_h);
    cudaGetSymbolAddress((void**)&hid_l, g_hid_l);
    cudaGetSymbolAddress((void**)&w,     g_w);
    cudaGetSymbolAddress((void**)&ctx_h, g_ctx_h);
    cudaGetSymbolAddress((void**)&ctx_l, g_ctx_l);
    cudaGetSymbolAddress((void**)&qh, g_qh);
    cudaGetSymbolAddress((void**)&kh, g_kh);
    cudaGetSymbolAddress((void**)&v,  g_v);

    int n4h = MM * HID / 4;
    split_h_kernel<<<(n4h + 255) / 256, 256>>>(hidden, hid_h, hid_l, n4h);

    int n4w = 4 * HID * HID / 4;
    convert_w_kernel<<<(n4w + 255) / 256, 256>>>(Wq, Wk, Wv, Wo, w);

    // fused Q/K/V projections with in-epilogue RoPE + fp16 quantization
    gemm_fp16_kernel<<<dim3(16, 32, 3), 256>>>(
        hid_h, hid_l,
        w + 0 * (size_t)HID * HID, w + 1 * (size_t)HID * HID, w + 2 * (size_t)HID * HID,
        cosT, sinT,
        (float*)0, qh, kh, v, /*mode=*/0);

    cudaFuncSetAttribute(attn_hmma_kernel, cudaFuncAttributeMaxDynamicSharedMemorySize, ATTN_SMEM);
    dim3 aGrid(SS / 128, NH, BB);
    attn_hmma_kernel<<<aGrid, 256, ATTN_SMEM>>>(qh, kh, v, ctx_h, ctx_l);

    // output projection -> fp32 out
    gemm_fp16_kernel<<<dim3(16, 32, 1), 256>>>(
        ctx_h, ctx_l,
        w + 3 * (size_t)HID * HID, (const __half*)0, (const __half*)0,
        cosT, sinT,
        out, (__half*)0, (__half*)0, (__half*)0, /*mode=*/1);
}

// round 8
// speedup vs baseline: 5.5817x; 1.4541x over previous
#include <cuda_runtime.h>
#include <cuda_fp16.h>
#include <cstdint>
#include <math.h>

#define BB 2
#define SS 2048
#define HID 1024
#define NH 16
#define DD 64
#define MM (BB*SS)          // 4096

// ---------------- scratch (no allocation allowed) ----------------
__device__ __half g_hid[MM*HID];
__device__ __half g_w[4][HID*HID];      // fp16 weights
__device__ __half g_ctx[MM*HID];

__device__ __half g_qh[MM*HID];
__device__ __half g_kh[MM*HID];
__device__ __half g_v[MM*HID];

// ================= helpers =================
__device__ __forceinline__ uint32_t smem_to_u32(const void* smem_ptr) {
    uint32_t addr;
    asm("{ .reg .u64 tmp; cvta.to.shared.u64 tmp, %1; cvt.u32.u64 %0, tmp; }"
        : "=r"(addr) : "l"(smem_ptr));
    return addr;
}
__device__ __forceinline__ void ldm_x4(uint32_t* r, uint32_t addr) {
    asm volatile("ldmatrix.sync.aligned.m8n8.x4.shared.b16 {%0,%1,%2,%3}, [%4];"
        : "=r"(r[0]), "=r"(r[1]), "=r"(r[2]), "=r"(r[3]) : "r"(addr));
}
__device__ __forceinline__ void ldm_x4_t(uint32_t* r, uint32_t addr) {
    asm volatile("ldmatrix.sync.aligned.m8n8.x4.trans.shared.b16 {%0,%1,%2,%3}, [%4];"
        : "=r"(r[0]), "=r"(r[1]), "=r"(r[2]), "=r"(r[3]) : "r"(addr));
}
__device__ __forceinline__ void mma16816h(float* c, const uint32_t* a, uint32_t b0, uint32_t b1) {
    asm volatile("mma.sync.aligned.m16n8k16.row.col.f32.f16.f16.f32 "
        "{%0,%1,%2,%3}, {%4,%5,%6,%7}, {%8,%9}, {%0,%1,%2,%3};"
        : "+f"(c[0]), "+f"(c[1]), "+f"(c[2]), "+f"(c[3])
        : "r"(a[0]), "r"(a[1]), "r"(a[2]), "r"(a[3]), "r"(b0), "r"(b1));
}
__device__ __forceinline__ void cp16(uint32_t saddr, const void* gaddr) {
    asm volatile("cp.async.cg.shared.global [%0], [%1], 16;" :: "r"(saddr), "l"(gaddr));
}
__device__ __forceinline__ void cp_commit() { asm volatile("cp.async.commit_group;" ::: "memory"); }
__device__ __forceinline__ void cp_wait0() { asm volatile("cp.async.wait_group 0;" ::: "memory"); }
__device__ __forceinline__ void cp_wait1() { asm volatile("cp.async.wait_group 1;" ::: "memory"); }

// ================= fp32 -> fp16 converts =================
__global__ void convert_kernel(const float* __restrict__ x, __half* __restrict__ y, int n4)
{
    int i = blockIdx.x * blockDim.x + threadIdx.x;
    if (i >= n4) return;
    float4 v = ((const float4*)x)[i];
    __half2* dp = (__half2*)y;
    dp[i * 2 + 0] = __floats2half2_rn(v.x, v.y);
    dp[i * 2 + 1] = __floats2half2_rn(v.z, v.w);
}
__global__ void convert_w_kernel(const float* __restrict__ w0, const float* __restrict__ w1,
                                 const float* __restrict__ w2, const float* __restrict__ w3,
                                 __half* __restrict__ dst)
{
    int i = blockIdx.x * blockDim.x + threadIdx.x;
    const int per = HID * HID / 4;
    if (i >= 4 * per) return;
    int wsel = i / per;
    int j = i - wsel * per;
    const float* src = (wsel == 0) ? w0 : (wsel == 1) ? w1 : (wsel == 2) ? w2 : w3;
    float4 v = ((const float4*)src)[j];
    __half2* dp = (__half2*)(dst + (size_t)wsel * HID * HID);
    dp[j * 2 + 0] = __floats2half2_rn(v.x, v.y);
    dp[j * 2 + 1] = __floats2half2_rn(v.z, v.w);
}

// ================= pipelined single-fp16 HMMA GEMM, tile 128x64 =================
// mode 0 (QKV): z0 -> rope+scale -> qout, z1 -> rope -> kout, z2 -> vout fp16
// mode 1 (Wo):  z0 -> fp32 c0
#define GROW 80
#define GA_B (128 * GROW)       // 10240
#define GB_B (64 * GROW)        // 5120
#define GSTG (GA_B + GB_B)      // 15360
#define GNIT (HID / 32)         // 32

__global__ __launch_bounds__(256, 2) void gemm_fp16_kernel(
    const __half* __restrict__ A,
    const __half* __restrict__ W0, const __half* __restrict__ W1,
    const __half* __restrict__ W2,
    const float* __restrict__ cosT, const float* __restrict__ sinT,
    float* __restrict__ c0,
    __half* __restrict__ qout, __half* __restrict__ kout, __half* __restrict__ vout,
    int mode)
{
    __shared__ __align__(16) unsigned char smem[2 * GSTG];

    const int tid  = threadIdx.x;
    const int wid  = tid >> 5;
    const int lane = tid & 31;
    const int wm   = wid >> 2;      // 0..1
    const int wn   = wid & 3;       // 0..3
    const int n0   = blockIdx.x * 64;
    const int m0   = blockIdx.y * 128;
    const int z    = blockIdx.z;

    const __half* B = (z == 0) ? W0 : (z == 1) ? W1 : W2;

    const uint32_t sb = smem_to_u32(smem);
    const int rL = tid >> 2;
    const int cL = tid & 3;

    auto load_stage = [&](int it, int buf) {
        const int k0 = it * 32;
        uint32_t st = sb + buf * GSTG;
#pragma unroll
        for (int half_ = 0; half_ < 2; half_++) {
            int row = rL + half_ * 64;
            size_t g = (size_t)(m0 + row) * HID + k0 + cL * 8;
            cp16(st + row * GROW + cL * 16, A + g);
        }
        {
            size_t g = (size_t)(n0 + rL) * HID + k0 + cL * 8;
            cp16(st + GA_B + rL * GROW + cL * 16, B + g);
        }
    };

    float acc[4][2][4];
#pragma unroll
    for (int i = 0; i < 4; i++)
#pragma unroll
        for (int j = 0; j < 2; j++)
#pragma unroll
            for (int r = 0; r < 4; r++) acc[i][j][r] = 0.0f;

    const int rowA  = lane & 15;
    const int kofsA = (lane >> 4) * 16;
    const int rowB  = (lane & 7) + ((lane >> 4) & 1) * 8;
    const int kofsB = ((lane >> 3) & 1) * 16;

    load_stage(0, 0);
    cp_commit();

    for (int it = 0; it < GNIT; it++) {
        const int cur = it & 1;
        cp_wait0();
        __syncthreads();
        if (it + 1 < GNIT) { load_stage(it + 1, cur ^ 1); cp_commit(); }

        const uint32_t sA = sb + cur * GSTG;
        const uint32_t sB = sA + GA_B;

#pragma unroll
        for (int kk = 0; kk < 2; kk++) {
            const int kb = kk * 32;
            uint32_t ah[4][4], b4[4];
#pragma unroll
            for (int mt = 0; mt < 4; mt++)
                ldm_x4(ah[mt], sA + (wm * 64 + mt * 16 + rowA) * GROW + kb + kofsA);
            ldm_x4(b4, sB + (wn * 16 + rowB) * GROW + kb + kofsB);
#pragma unroll
            for (int mt = 0; mt < 4; mt++) {
                mma16816h(acc[mt][0], ah[mt], b4[0], b4[1]);
                mma16816h(acc[mt][1], ah[mt], b4[2], b4[3]);
            }
        }
        __syncthreads();
    }

    const int rr = lane >> 2;
    const int cc = (lane & 3) * 2;

    if (mode == 1) {
#pragma unroll
        for (int mt = 0; mt < 4; mt++)
#pragma unroll
            for (int nt = 0; nt < 2; nt++) {
                int r = m0 + wm * 64 + mt * 16 + rr;
                int c = n0 + wn * 16 + nt * 8 + cc;
                *(float2*)&c0[(size_t)r * HID + c] =
                    make_float2(acc[mt][nt][0], acc[mt][nt][1]);
                *(float2*)&c0[(size_t)(r + 8) * HID + c] =
                    make_float2(acc[mt][nt][2], acc[mt][nt][3]);
            }
        return;
    }

    if (z == 2) {
#pragma unroll
        for (int mt = 0; mt < 4; mt++)
#pragma unroll
            for (int nt = 0; nt < 2; nt++) {
                int r = m0 + wm * 64 + mt * 16 + rr;
                int c = n0 + wn * 16 + nt * 8 + cc;
#pragma unroll
                for (int half_ = 0; half_ < 2; half_++) {
                    size_t idx = (size_t)(r + half_ * 8) * HID + c;
                    *(__half2*)&vout[idx] =
                        __floats2half2_rn(acc[mt][nt][half_ * 2], acc[mt][nt][half_ * 2 + 1]);
                }
            }
    } else {
        __half* dst = (z == 0) ? qout : kout;
        const float scale = (z == 0) ? 0.125f : 1.0f;
#pragma unroll
        for (int mt = 0; mt < 4; mt++)
#pragma unroll
            for (int nt = 0; nt < 2; nt++) {
                int c = n0 + wn * 16 + nt * 8 + cc;       // even
                int p = (c & 63) >> 1;
#pragma unroll
                for (int half_ = 0; half_ < 2; half_++) {
                    int r = m0 + wm * 64 + mt * 16 + rr + half_ * 8;
                    int s = r & (SS - 1);
                    float co = cosT[s * 32 + p];
                    float si = sinT[s * 32 + p];
                    float a = acc[mt][nt][half_ * 2];
                    float b = acc[mt][nt][half_ * 2 + 1];
                    float o0 = (a * co - b * si) * scale;
                    float o1 = (a * si + b * co) * scale;
                    *(__half2*)&dst[(size_t)r * HID + c] = __floats2half2_rn(o0, o1);
                }
            }
    }
}

// ---------------- fp16 HMMA flash attention (causal) ----------------
#define ASTR 144
#define AQB  (128 * ASTR)       // 18432
#define AKB  (64 * ASTR)        // 9216
#define AKVSTG (2 * AKB)        // 18432
#define ATTN_SMEM (AQB + 2 * AKVSTG)   // 55296

__global__ __launch_bounds__(256, 2) void attn_hmma_kernel(
    const __half* __restrict__ qh, const __half* __restrict__ kh,
    const __half* __restrict__ vv,
    __half* __restrict__ ctxh)
{
    extern __shared__ unsigned char sm[];
    // schedule heavy CTAs first: qi descending in launch order
    const int qi  = (int)gridDim.x - 1 - (int)blockIdx.x;
    const int h   = blockIdx.y;
    const int b   = blockIdx.z;
    const int tid = threadIdx.x;
    const int wid = tid >> 5;
    const int lane = tid & 31;
    const int q0  = qi * 128;

    const uint32_t sb  = smem_to_u32(sm);
    const uint32_t sQh = sb;
    const uint32_t sKV = sb + AQB;

    const int ntiles = 2 * qi + 2;

    {
        int row = tid >> 1;
        int c   = (tid & 1) * 4;
        size_t g = ((size_t)(b * SS + q0 + row) * NH + h) * DD;
#pragma unroll
        for (int j = 0; j < 4; j++)
            cp16(sQh + row * ASTR + (c + j) * 16, qh + g + (c + j) * 8);
    }
    auto loadKV = [&](int jt, int buf) {
        uint32_t base = sKV + buf * AKVSTG;
        int row = tid >> 2;
        int c   = (tid & 3) * 2;
        size_t g = ((size_t)(b * SS + jt * 64 + row) * NH + h) * DD;
#pragma unroll
        for (int j = 0; j < 2; j++) {
            uint32_t so = row * ASTR + (c + j) * 16;
            size_t go = g + (c + j) * 8;
            cp16(base + so,       kh + go);
            cp16(base + AKB + so, vv + go);
        }
    };
    loadKV(0, 0);
    cp_commit();
    if (ntiles > 1) { loadKV(1, 1); cp_commit(); cp_wait1(); }
    else cp_wait0();
    __syncthreads();

    float mrow[2] = {-1e30f, -1e30f};
    float lrow[2] = {0.0f, 0.0f};
    float oacc[8][4];
#pragma unroll
    for (int nt = 0; nt < 8; nt++)
#pragma unroll
        for (int r = 0; r < 4; r++) oacc[nt][r] = 0.0f;

    const int rowA  = lane & 15;
    const int kofsA = (lane >> 4) * 16;
    const int rowB  = (lane & 7) + ((lane >> 4) & 1) * 8;
    const int kofsB = ((lane >> 3) & 1) * 16;

    for (int jt = 0; jt < ntiles; jt++) {
        const int cur = jt & 1;
        const uint32_t bK = sKV + cur * AKVSTG;
        const uint32_t bV = bK + AKB;

        float sc[8][4];
#pragma unroll
        for (int nt = 0; nt < 8; nt++)
#pragma unroll
            for (int r = 0; r < 4; r++) sc[nt][r] = 0.0f;

#pragma unroll
        for (int ks = 0; ks < 4; ks++) {
            uint32_t ah[4];
            ldm_x4(ah, sQh + (wid * 16 + rowA) * ASTR + ks * 32 + kofsA);
#pragma unroll
            for (int nt2 = 0; nt2 < 4; nt2++) {
                uint32_t b4[4];
                ldm_x4(b4, bK + (nt2 * 16 + rowB) * ASTR + ks * 32 + kofsB);
                mma16816h(sc[2 * nt2],     ah, b4[0], b4[1]);
                mma16816h(sc[2 * nt2 + 1], ah, b4[2], b4[3]);
            }
        }

        const int kv0 = jt * 64;
        if (kv0 + 63 > q0 + wid * 16) {
            const int qr = q0 + wid * 16 + (lane >> 2);
#pragma unroll
            for (int nt = 0; nt < 8; nt++) {
#pragma unroll
                for (int r = 0; r < 4; r++) {
                    int qrow = qr + ((r >= 2) ? 8 : 0);
                    int kvc  = kv0 + nt * 8 + (lane & 3) * 2 + (r & 1);
                    if (kvc > qrow) sc[nt][r] = -1e30f;
                }
            }
        }

#pragma unroll
        for (int rh = 0; rh < 2; rh++) {
            float mx = -1e30f;
#pragma unroll
            for (int nt = 0; nt < 8; nt++)
                mx = fmaxf(mx, fmaxf(sc[nt][rh * 2], sc[nt][rh * 2 + 1]));
            mx = fmaxf(mx, __shfl_xor_sync(0xffffffffu, mx, 1));
            mx = fmaxf(mx, __shfl_xor_sync(0xffffffffu, mx, 2));
            float mn = fmaxf(mrow[rh], mx);
            float alpha = __expf(mrow[rh] - mn);
            mrow[rh] = mn;
            float sum = 0.0f;
#pragma unroll
            for (int nt = 0; nt < 8; nt++) {
                float p0 = __expf(sc[nt][rh * 2]     - mn);
                float p1 = __expf(sc[nt][rh * 2 + 1] - mn);
                sc[nt][rh * 2]     = p0;
                sc[nt][rh * 2 + 1] = p1;
                sum += p0 + p1;
            }
            sum += __shfl_xor_sync(0xffffffffu, sum, 1);
            sum += __shfl_xor_sync(0xffffffffu, sum, 2);
            lrow[rh] = lrow[rh] * alpha + sum;
#pragma unroll
            for (int nt = 0; nt < 8; nt++) {
                oacc[nt][rh * 2]     *= alpha;
                oacc[nt][rh * 2 + 1] *= alpha;
            }
        }

        uint32_t ph[4][4];
#pragma unroll
        for (int ks2 = 0; ks2 < 4; ks2++) {
            const int na = 2 * ks2, nb = 2 * ks2 + 1;
            __half2 t0 = __floats2half2_rn(sc[na][0], sc[na][1]);
            __half2 t1 = __floats2half2_rn(sc[na][2], sc[na][3]);
            __half2 t2 = __floats2half2_rn(sc[nb][0], sc[nb][1]);
            __half2 t3 = __floats2half2_rn(sc[nb][2], sc[nb][3]);
            ph[ks2][0] = *(uint32_t*)&t0;
            ph[ks2][1] = *(uint32_t*)&t1;
            ph[ks2][2] = *(uint32_t*)&t2;
            ph[ks2][3] = *(uint32_t*)&t3;
        }

#pragma unroll
        for (int ks2 = 0; ks2 < 4; ks2++) {
#pragma unroll
            for (int nt2 = 0; nt2 < 4; nt2++) {
                uint32_t bv[4];
                uint32_t voff = (ks2 * 16 + (lane & 15)) * ASTR + (nt2 * 16 + (lane >> 4) * 8) * 2;
                ldm_x4_t(bv, bV + voff);
                mma16816h(oacc[2 * nt2],     ph[ks2], bv[0], bv[1]);
                mma16816h(oacc[2 * nt2 + 1], ph[ks2], bv[2], bv[3]);
            }
        }

        if (jt + 1 < ntiles) {
            __syncthreads();
            if (jt + 2 < ntiles) { loadKV(jt + 2, cur); cp_commit(); cp_wait1(); }
            else cp_wait0();
            __syncthreads();
        }
    }

    // epilogue: single fp16 ctx
#pragma unroll
    for (int rh = 0; rh < 2; rh++) {
        float inv = 1.0f / lrow[rh];
        int row = q0 + wid * 16 + (lane >> 2) + rh * 8;
        size_t base = ((size_t)(b * SS + row) * NH + h) * DD;
#pragma unroll
        for (int nt = 0; nt < 8; nt++) {
            float x0 = oacc[nt][rh * 2] * inv;
            float x1 = oacc[nt][rh * 2 + 1] * inv;
            *(__half2*)&ctxh[base + nt * 8 + (lane & 3) * 2] = __floats2half2_rn(x0, x1);
        }
    }
}

// ---------------- host ----------------
extern "C" void kernel_launch(void* const* d_in, const int* in_sizes, int n_in,
                              void* d_out, int out_size)
{
    const float* hidden = (const float*)d_in[0];
    const float* cosT   = (const float*)d_in[1];
    const float* sinT   = (const float*)d_in[2];
    const float* Wq = (const float*)d_in[4];
    const float* Wk = (const float*)d_in[5];
    const float* Wv = (const float*)d_in[6];
    const float* Wo = (const float*)d_in[7];
    float* out = (float*)d_out;

    __half *hid, *w, *ctx, *qh, *kh, *v;
    cudaGetSymbolAddress((void**)&hid, g_hid);
    cudaGetSymbolAddress((void**)&w,   g_w);
    cudaGetSymbolAddress((void**)&ctx, g_ctx);
    cudaGetSymbolAddress((void**)&qh, g_qh);
    cudaGetSymbolAddress((void**)&kh, g_kh);
    cudaGetSymbolAddress((void**)&v,  g_v);

    int n4h = MM * HID / 4;
    convert_kernel<<<(n4h + 255) / 256, 256>>>(hidden, hid, n4h);

    int n4w = 4 * HID * HID / 4;
    convert_w_kernel<<<(n4w + 255) / 256, 256>>>(Wq, Wk, Wv, Wo, w);

    // fused Q/K/V projections with in-epilogue RoPE + fp16 quantization
    gemm_fp16_kernel<<<dim3(16, 32, 3), 256>>>(
        hid,
        w + 0 * (size_t)HID * HID, w + 1 * (size_t)HID * HID, w + 2 * (size_t)HID * HID,
        cosT, sinT,
        (float*)0, qh, kh, v, /*mode=*/0);

    cudaFuncSetAttribute(attn_hmma_kernel, cudaFuncAttributeMaxDynamicSharedMemorySize, ATTN_SMEM);
    dim3 aGrid(SS / 128, NH, BB);
    attn_hmma_kernel<<<aGrid, 256, ATTN_SMEM>>>(qh, kh, v, ctx);

    // output projection -> fp32 out
    gemm_fp16_kernel<<<dim3(16, 32, 1), 256>>>(
        ctx,
        w + 3 * (size_t)HID * HID, (const __half*)0, (const __half*)0,
        cosT, sinT,
        out, (__half*)0, (__half*)0, (__half*)0, /*mode=*/1);
}

// round 9
// speedup vs baseline: 5.9111x; 1.0590x over previous
#include <cuda_runtime.h>
#include <cuda_fp16.h>
#include <cstdint>
#include <math.h>

#define BB 2
#define SS 2048
#define HID 1024
#define NH 16
#define DD 64
#define MM (BB*SS)          // 4096
#define NQT (SS/128)        // 16 q-tiles per (b,h)

// ---------------- scratch (no allocation allowed) ----------------
__device__ __half g_hid[MM*HID];
__device__ __half g_w[4][HID*HID];
__device__ __half g_ctx[MM*HID];

__device__ __half g_qh[MM*HID];
__device__ __half g_kh[MM*HID];
__device__ __half g_v[MM*HID];

// ================= helpers =================
__device__ __forceinline__ uint32_t smem_to_u32(const void* smem_ptr) {
    uint32_t addr;
    asm("{ .reg .u64 tmp; cvta.to.shared.u64 tmp, %1; cvt.u32.u64 %0, tmp; }"
        : "=r"(addr) : "l"(smem_ptr));
    return addr;
}
__device__ __forceinline__ void ldm_x4(uint32_t* r, uint32_t addr) {
    asm volatile("ldmatrix.sync.aligned.m8n8.x4.shared.b16 {%0,%1,%2,%3}, [%4];"
        : "=r"(r[0]), "=r"(r[1]), "=r"(r[2]), "=r"(r[3]) : "r"(addr));
}
__device__ __forceinline__ void ldm_x4_t(uint32_t* r, uint32_t addr) {
    asm volatile("ldmatrix.sync.aligned.m8n8.x4.trans.shared.b16 {%0,%1,%2,%3}, [%4];"
        : "=r"(r[0]), "=r"(r[1]), "=r"(r[2]), "=r"(r[3]) : "r"(addr));
}
__device__ __forceinline__ void mma16816h(float* c, const uint32_t* a, uint32_t b0, uint32_t b1) {
    asm volatile("mma.sync.aligned.m16n8k16.row.col.f32.f16.f16.f32 "
        "{%0,%1,%2,%3}, {%4,%5,%6,%7}, {%8,%9}, {%0,%1,%2,%3};"
        : "+f"(c[0]), "+f"(c[1]), "+f"(c[2]), "+f"(c[3])
        : "r"(a[0]), "r"(a[1]), "r"(a[2]), "r"(a[3]), "r"(b0), "r"(b1));
}
__device__ __forceinline__ void cp16(uint32_t saddr, const void* gaddr) {
    asm volatile("cp.async.cg.shared.global [%0], [%1], 16;" :: "r"(saddr), "l"(gaddr));
}
__device__ __forceinline__ void cp_commit() { asm volatile("cp.async.commit_group;" ::: "memory"); }
__device__ __forceinline__ void cp_wait0() { asm volatile("cp.async.wait_group 0;" ::: "memory"); }
__device__ __forceinline__ void cp_wait1() { asm volatile("cp.async.wait_group 1;" ::: "memory"); }
__device__ __forceinline__ float fexp2(float x) {
    float y; asm("ex2.approx.f32 %0, %1;" : "=f"(y) : "f"(x)); return y;
}

// ================= fp32 -> fp16 convert: hidden + 4 weights in one launch =================
__global__ void convert_all_kernel(const float* __restrict__ hid_f,
                                   const float* __restrict__ w0, const float* __restrict__ w1,
                                   const float* __restrict__ w2, const float* __restrict__ w3,
                                   __half* __restrict__ hid_h, __half* __restrict__ w_h)
{
    const int nh4 = MM * HID / 4;          // 1M
    const int nw4 = HID * HID / 4;         // 256K per weight
    int i = blockIdx.x * blockDim.x + threadIdx.x;
    const float* src;
    __half2* dst;
    int j;
    if (i < nh4) {
        src = hid_f; dst = (__half2*)hid_h; j = i;
    } else {
        int t = i - nh4;
        if (t >= 4 * nw4) return;
        int wsel = t / nw4;
        j = t - wsel * nw4;
        src = (wsel == 0) ? w0 : (wsel == 1) ? w1 : (wsel == 2) ? w2 : w3;
        dst = (__half2*)(w_h + (size_t)wsel * HID * HID);
    }
    float4 v = ((const float4*)src)[j];
    dst[j * 2 + 0] = __floats2half2_rn(v.x, v.y);
    dst[j * 2 + 1] = __floats2half2_rn(v.z, v.w);
}

// ================= pipelined single-fp16 HMMA GEMM, tile 128x64 =================
#define GROW 80
#define GA_B (128 * GROW)
#define GB_B (64 * GROW)
#define GSTG (GA_B + GB_B)
#define GNIT (HID / 32)

__global__ __launch_bounds__(256, 2) void gemm_fp16_kernel(
    const __half* __restrict__ A,
    const __half* __restrict__ W0, const __half* __restrict__ W1,
    const __half* __restrict__ W2,
    const float* __restrict__ cosT, const float* __restrict__ sinT,
    float* __restrict__ c0,
    __half* __restrict__ qout, __half* __restrict__ kout, __half* __restrict__ vout,
    int mode)
{
    __shared__ __align__(16) unsigned char smem[2 * GSTG];

    const int tid  = threadIdx.x;
    const int wid  = tid >> 5;
    const int lane = tid & 31;
    const int wm   = wid >> 2;
    const int wn   = wid & 3;
    const int n0   = blockIdx.x * 64;
    const int m0   = blockIdx.y * 128;
    const int z    = blockIdx.z;

    const __half* B = (z == 0) ? W0 : (z == 1) ? W1 : W2;

    const uint32_t sb = smem_to_u32(smem);
    const int rL = tid >> 2;
    const int cL = tid & 3;

    auto load_stage = [&](int it, int buf) {
        const int k0 = it * 32;
        uint32_t st = sb + buf * GSTG;
#pragma unroll
        for (int half_ = 0; half_ < 2; half_++) {
            int row = rL + half_ * 64;
            size_t g = (size_t)(m0 + row) * HID + k0 + cL * 8;
            cp16(st + row * GROW + cL * 16, A + g);
        }
        {
            size_t g = (size_t)(n0 + rL) * HID + k0 + cL * 8;
            cp16(st + GA_B + rL * GROW + cL * 16, B + g);
        }
    };

    float acc[4][2][4];
#pragma unroll
    for (int i = 0; i < 4; i++)
#pragma unroll
        for (int j = 0; j < 2; j++)
#pragma unroll
            for (int r = 0; r < 4; r++) acc[i][j][r] = 0.0f;

    const int rowA  = lane & 15;
    const int kofsA = (lane >> 4) * 16;
    const int rowB  = (lane & 7) + ((lane >> 4) & 1) * 8;
    const int kofsB = ((lane >> 3) & 1) * 16;

    load_stage(0, 0);
    cp_commit();

    for (int it = 0; it < GNIT; it++) {
        const int cur = it & 1;
        cp_wait0();
        __syncthreads();
        if (it + 1 < GNIT) { load_stage(it + 1, cur ^ 1); cp_commit(); }

        const uint32_t sA = sb + cur * GSTG;
        const uint32_t sB = sA + GA_B;

#pragma unroll
        for (int kk = 0; kk < 2; kk++) {
            const int kb = kk * 32;
            uint32_t ah[4][4], b4[4];
#pragma unroll
            for (int mt = 0; mt < 4; mt++)
                ldm_x4(ah[mt], sA + (wm * 64 + mt * 16 + rowA) * GROW + kb + kofsA);
            ldm_x4(b4, sB + (wn * 16 + rowB) * GROW + kb + kofsB);
#pragma unroll
            for (int mt = 0; mt < 4; mt++) {
                mma16816h(acc[mt][0], ah[mt], b4[0], b4[1]);
                mma16816h(acc[mt][1], ah[mt], b4[2], b4[3]);
            }
        }
        __syncthreads();
    }

    const int rr = lane >> 2;
    const int cc = (lane & 3) * 2;

    if (mode == 1) {
#pragma unroll
        for (int mt = 0; mt < 4; mt++)
#pragma unroll
            for (int nt = 0; nt < 2; nt++) {
                int r = m0 + wm * 64 + mt * 16 + rr;
                int c = n0 + wn * 16 + nt * 8 + cc;
                *(float2*)&c0[(size_t)r * HID + c] =
                    make_float2(acc[mt][nt][0], acc[mt][nt][1]);
                *(float2*)&c0[(size_t)(r + 8) * HID + c] =
                    make_float2(acc[mt][nt][2], acc[mt][nt][3]);
            }
        return;
    }

    if (z == 2) {
#pragma unroll
        for (int mt = 0; mt < 4; mt++)
#pragma unroll
            for (int nt = 0; nt < 2; nt++) {
                int r = m0 + wm * 64 + mt * 16 + rr;
                int c = n0 + wn * 16 + nt * 8 + cc;
#pragma unroll
                for (int half_ = 0; half_ < 2; half_++) {
                    size_t idx = (size_t)(r + half_ * 8) * HID + c;
                    *(__half2*)&vout[idx] =
                        __floats2half2_rn(acc[mt][nt][half_ * 2], acc[mt][nt][half_ * 2 + 1]);
                }
            }
    } else {
        // q folded with 0.125 * log2(e) so softmax can use raw ex2
        __half* dst = (z == 0) ? qout : kout;
        const float scale = (z == 0) ? 0.125f * 1.4426950408889634f : 1.0f;
#pragma unroll
        for (int mt = 0; mt < 4; mt++)
#pragma unroll
            for (int nt = 0; nt < 2; nt++) {
                int c = n0 + wn * 16 + nt * 8 + cc;
                int p = (c & 63) >> 1;
#pragma unroll
                for (int half_ = 0; half_ < 2; half_++) {
                    int r = m0 + wm * 64 + mt * 16 + rr + half_ * 8;
                    int s = r & (SS - 1);
                    float co = cosT[s * 32 + p];
                    float si = sinT[s * 32 + p];
                    float a = acc[mt][nt][half_ * 2];
                    float b = acc[mt][nt][half_ * 2 + 1];
                    float o0 = (a * co - b * si) * scale;
                    float o1 = (a * si + b * co) * scale;
                    *(__half2*)&dst[(size_t)r * HID + c] = __floats2half2_rn(o0, o1);
                }
            }
    }
}

// ---------------- fp16 HMMA flash attention (causal, qi-paired) ----------------
// CTA processes q-tiles {NQT-1-pid, pid}: constant 34 KV-tiles per CTA, single wave.
#define ASTR 144
#define AQB  (128 * ASTR)
#define AKB  (64 * ASTR)
#define AKVSTG (2 * AKB)
#define ATTN_SMEM (AQB + 2 * AKVSTG)   // 55296

__global__ __launch_bounds__(256, 2) void attn_hmma_kernel(
    const __half* __restrict__ qh, const __half* __restrict__ kh,
    const __half* __restrict__ vv,
    __half* __restrict__ ctxh)
{
    extern __shared__ unsigned char sm[];
    const int pid = blockIdx.x;          // 0..NQT/2-1
    const int h   = blockIdx.y;
    const int b   = blockIdx.z;
    const int tid = threadIdx.x;
    const int wid = tid >> 5;
    const int lane = tid & 31;

    const uint32_t sb  = smem_to_u32(sm);
    const uint32_t sQh = sb;
    const uint32_t sKV = sb + AQB;

    const int rowA  = lane & 15;
    const int kofsA = (lane >> 4) * 16;
    const int rowB  = (lane & 7) + ((lane >> 4) & 1) * 8;
    const int kofsB = ((lane >> 3) & 1) * 16;

#pragma unroll 1
    for (int phase = 0; phase < 2; phase++) {
        const int qi = (phase == 0) ? (NQT - 1 - pid) : pid;   // heavy first
        const int q0 = qi * 128;
        const int ntiles = 2 * qi + 2;                          // >= 2

        if (phase) __syncthreads();    // previous phase done with smem

        // Q load
        {
            int row = tid >> 1;
            int c   = (tid & 1) * 4;
            size_t g = ((size_t)(b * SS + q0 + row) * NH + h) * DD;
#pragma unroll
            for (int j = 0; j < 4; j++)
                cp16(sQh + row * ASTR + (c + j) * 16, qh + g + (c + j) * 8);
        }
        auto loadKV = [&](int jt, int buf) {
            uint32_t base = sKV + buf * AKVSTG;
            int row = tid >> 2;
            int c   = (tid & 3) * 2;
            size_t g = ((size_t)(b * SS + jt * 64 + row) * NH + h) * DD;
#pragma unroll
            for (int j = 0; j < 2; j++) {
                uint32_t so = row * ASTR + (c + j) * 16;
                size_t go = g + (c + j) * 8;
                cp16(base + so,       kh + go);
                cp16(base + AKB + so, vv + go);
            }
        };
        loadKV(0, 0);
        cp_commit();
        loadKV(1, 1);
        cp_commit();
        cp_wait1();
        __syncthreads();

        float mrow[2] = {-1e30f, -1e30f};
        float lrow[2] = {0.0f, 0.0f};
        float oacc[8][4];
#pragma unroll
        for (int nt = 0; nt < 8; nt++)
#pragma unroll
            for (int r = 0; r < 4; r++) oacc[nt][r] = 0.0f;

        for (int jt = 0; jt < ntiles; jt++) {
            const int cur = jt & 1;
            const uint32_t bK = sKV + cur * AKVSTG;
            const uint32_t bV = bK + AKB;
            const int kv0 = jt * 64;
            const int qtop = q0 + wid * 16 + 15;   // highest q-row this warp owns

            if (kv0 <= qtop) {   // skip fully-masked warp-tiles
                float sc[8][4];
#pragma unroll
                for (int nt = 0; nt < 8; nt++)
#pragma unroll
                    for (int r = 0; r < 4; r++) sc[nt][r] = 0.0f;

#pragma unroll
                for (int ks = 0; ks < 4; ks++) {
                    uint32_t ah[4];
                    ldm_x4(ah, sQh + (wid * 16 + rowA) * ASTR + ks * 32 + kofsA);
#pragma unroll
                    for (int nt2 = 0; nt2 < 4; nt2++) {
                        uint32_t b4[4];
                        ldm_x4(b4, bK + (nt2 * 16 + rowB) * ASTR + ks * 32 + kofsB);
                        mma16816h(sc[2 * nt2],     ah, b4[0], b4[1]);
                        mma16816h(sc[2 * nt2 + 1], ah, b4[2], b4[3]);
                    }
                }

                if (kv0 + 63 > q0 + wid * 16) {
                    const int qr = q0 + wid * 16 + (lane >> 2);
#pragma unroll
                    for (int nt = 0; nt < 8; nt++) {
#pragma unroll
                        for (int r = 0; r < 4; r++) {
                            int qrow = qr + ((r >= 2) ? 8 : 0);
                            int kvc  = kv0 + nt * 8 + (lane & 3) * 2 + (r & 1);
                            if (kvc > qrow) sc[nt][r] = -1e30f;
                        }
                    }
                }

#pragma unroll
                for (int rh = 0; rh < 2; rh++) {
                    float mx = -1e30f;
#pragma unroll
                    for (int nt = 0; nt < 8; nt++)
                        mx = fmaxf(mx, fmaxf(sc[nt][rh * 2], sc[nt][rh * 2 + 1]));
                    mx = fmaxf(mx, __shfl_xor_sync(0xffffffffu, mx, 1));
                    mx = fmaxf(mx, __shfl_xor_sync(0xffffffffu, mx, 2));
                    float mn = fmaxf(mrow[rh], mx);
                    float alpha = fexp2(mrow[rh] - mn);
                    mrow[rh] = mn;
                    float sum = 0.0f;
#pragma unroll
                    for (int nt = 0; nt < 8; nt++) {
                        float p0 = fexp2(sc[nt][rh * 2]     - mn);
                        float p1 = fexp2(sc[nt][rh * 2 + 1] - mn);
                        sc[nt][rh * 2]     = p0;
                        sc[nt][rh * 2 + 1] = p1;
                        sum += p0 + p1;
                    }
                    sum += __shfl_xor_sync(0xffffffffu, sum, 1);
                    sum += __shfl_xor_sync(0xffffffffu, sum, 2);
                    lrow[rh] = lrow[rh] * alpha + sum;
#pragma unroll
                    for (int nt = 0; nt < 8; nt++) {
                        oacc[nt][rh * 2]     *= alpha;
                        oacc[nt][rh * 2 + 1] *= alpha;
                    }
                }

                uint32_t ph[4][4];
#pragma unroll
                for (int ks2 = 0; ks2 < 4; ks2++) {
                    const int na = 2 * ks2, nb = 2 * ks2 + 1;
                    __half2 t0 = __floats2half2_rn(sc[na][0], sc[na][1]);
                    __half2 t1 = __floats2half2_rn(sc[na][2], sc[na][3]);
                    __half2 t2 = __floats2half2_rn(sc[nb][0], sc[nb][1]);
                    __half2 t3 = __floats2half2_rn(sc[nb][2], sc[nb][3]);
                    ph[ks2][0] = *(uint32_t*)&t0;
                    ph[ks2][1] = *(uint32_t*)&t1;
                    ph[ks2][2] = *(uint32_t*)&t2;
                    ph[ks2][3] = *(uint32_t*)&t3;
                }

#pragma unroll
                for (int ks2 = 0; ks2 < 4; ks2++) {
#pragma unroll
                    for (int nt2 = 0; nt2 < 4; nt2++) {
                        uint32_t bv[4];
                        uint32_t voff = (ks2 * 16 + (lane & 15)) * ASTR + (nt2 * 16 + (lane >> 4) * 8) * 2;
                        ldm_x4_t(bv, bV + voff);
                        mma16816h(oacc[2 * nt2],     ph[ks2], bv[0], bv[1]);
                        mma16816h(oacc[2 * nt2 + 1], ph[ks2], bv[2], bv[3]);
                    }
                }
            }

            if (jt + 1 < ntiles) {
                __syncthreads();
                if (jt + 2 < ntiles) { loadKV(jt + 2, cur); cp_commit(); cp_wait1(); }
                else cp_wait0();
                __syncthreads();
            }
        }

        // epilogue
#pragma unroll
        for (int rh = 0; rh < 2; rh++) {
            float inv = 1.0f / lrow[rh];
            int row = q0 + wid * 16 + (lane >> 2) + rh * 8;
            size_t base = ((size_t)(b * SS + row) * NH + h) * DD;
#pragma unroll
            for (int nt = 0; nt < 8; nt++) {
                float x0 = oacc[nt][rh * 2] * inv;
                float x1 = oacc[nt][rh * 2 + 1] * inv;
                *(__half2*)&ctxh[base + nt * 8 + (lane & 3) * 2] = __floats2half2_rn(x0, x1);
            }
        }
    }
}

// ---------------- host ----------------
extern "C" void kernel_launch(void* const* d_in, const int* in_sizes, int n_in,
                              void* d_out, int out_size)
{
    const float* hidden = (const float*)d_in[0];
    const float* cosT   = (const float*)d_in[1];
    const float* sinT   = (const float*)d_in[2];
    const float* Wq = (const float*)d_in[4];
    const float* Wk = (const float*)d_in[5];
    const float* Wv = (const float*)d_in[6];
    const float* Wo = (const float*)d_in[7];
    float* out = (float*)d_out;

    __half *hid, *w, *ctx, *qh, *kh, *v;
    cudaGetSymbolAddress((void**)&hid, g_hid);
    cudaGetSymbolAddress((void**)&w,   g_w);
    cudaGetSymbolAddress((void**)&ctx, g_ctx);
    cudaGetSymbolAddress((void**)&qh, g_qh);
    cudaGetSymbolAddress((void**)&kh, g_kh);
    cudaGetSymbolAddress((void**)&v,  g_v);

    int ncv = MM * HID / 4 + 4 * (HID * HID / 4);   // 2M float4 units
    convert_all_kernel<<<(ncv + 255) / 256, 256>>>(hidden, Wq, Wk, Wv, Wo, hid, w);

    // fused Q/K/V projections with in-epilogue RoPE (+ log2e fold) + fp16 quantization
    gemm_fp16_kernel<<<dim3(16, 32, 3), 256>>>(
        hid,
        w + 0 * (size_t)HID * HID, w + 1 * (size_t)HID * HID, w + 2 * (size_t)HID * HID,
        cosT, sinT,
        (float*)0, qh, kh, v, /*mode=*/0);

    cudaFuncSetAttribute(attn_hmma_kernel, cudaFuncAttributeMaxDynamicSharedMemorySize, ATTN_SMEM);
    dim3 aGrid(NQT / 2, NH, BB);   // (8, 16, 2) = 256 CTAs, single wave
    attn_hmma_kernel<<<aGrid, 256, ATTN_SMEM>>>(qh, kh, v, ctx);

    // output projection -> fp32 out
    gemm_fp16_kernel<<<dim3(16, 32, 1), 256>>>(
        ctx,
        w + 3 * (size_t)HID * HID, (const __half*)0, (const __half*)0,
        cosT, sinT,
        out, (__half*)0, (__half*)0, (__half*)0, /*mode=*/1);
}